// round 1
// baseline (speedup 1.0000x reference)
#include <cuda_runtime.h>
#include <math.h>

#define Bsz 256
#define Ssz 128
#define Fsz 128
#define Hsz 512
#define G4H 2048
#define Csz 64
#define Lsz 16

// ---------------- device scratch (no allocations allowed) ----------------
__device__ float g_h[2][Bsz * Hsz];     // double-buffered hidden state
__device__ float g_c[Bsz * Hsz];        // cell state (owner-exclusive per (b,j))
__device__ float g_ctx[Bsz * 3 * Hsz];  // sigmoid context gates [ci|cf|co] per row
__device__ float g_t1[Bsz * Hsz];       // relu(context@cg_w1+b)
__device__ float g_z[Bsz * Lsz];        // reparameterized latent

__device__ __forceinline__ float sigmoidf_(float v) { return 1.0f / (1.0f + expf(-v)); }

// ---------------- init: zero h0 and c ----------------
__global__ void init_kernel() {
    int i = blockIdx.x * blockDim.x + threadIdx.x;
    if (i < Bsz * Hsz) { g_h[0][i] = 0.0f; g_c[i] = 0.0f; }
}

// ---------------- context-gate GEMMs ----------------
// mode 0: g_t1 = relu(context[256,64] @ cg_w1[64,512] + b)        grid (8,4)
// mode 1: g_ctx = sigmoid(g_t1[256,512] @ cg_w2[512,1536] + b)    grid (24,4)
__global__ __launch_bounds__(256) void ctx_gemm_kernel(
    const float* __restrict__ Aext, const float* __restrict__ W,
    const float* __restrict__ bias, int mode)
{
    const int K   = (mode == 0) ? 64 : 512;
    const int lda = (mode == 0) ? 64 : 512;
    const int ldw = (mode == 0) ? 512 : 1536;
    const int ldc = ldw;
    const float* A = (mode == 0) ? Aext : g_t1;
    float* Cout    = (mode == 0) ? g_t1 : g_ctx;

    const int n0 = blockIdx.x * 64;
    const int m0 = blockIdx.y * 64;
    const int tid = threadIdx.x;
    const int tc = tid & 15;   // col group: cols n0 + tc*4 .. +3
    const int rg = tid >> 4;   // row group: rows m0 + rg*4 .. +3

    __shared__ float As[16][68];
    __shared__ float Ws[16][68];

    float4 acc[4];
#pragma unroll
    for (int i = 0; i < 4; i++) acc[i] = make_float4(0.f, 0.f, 0.f, 0.f);

    for (int k0 = 0; k0 < K; k0 += 16) {
#pragma unroll
        for (int u = 0; u < 4; u++) {
            int i = tid + u * 256;
            int r = i >> 4, kk = i & 15;
            As[kk][r] = A[(m0 + r) * lda + k0 + kk];
            int kr = i >> 6, c = i & 63;
            Ws[kr][c] = W[(k0 + kr) * ldw + n0 + c];
        }
        __syncthreads();
#pragma unroll
        for (int kk = 0; kk < 16; kk++) {
            float4 w = *(const float4*)&Ws[kk][tc * 4];
            float4 a = *(const float4*)&As[kk][rg * 4];
            acc[0].x += a.x * w.x; acc[0].y += a.x * w.y; acc[0].z += a.x * w.z; acc[0].w += a.x * w.w;
            acc[1].x += a.y * w.x; acc[1].y += a.y * w.y; acc[1].z += a.y * w.z; acc[1].w += a.y * w.w;
            acc[2].x += a.z * w.x; acc[2].y += a.z * w.y; acc[2].z += a.z * w.z; acc[2].w += a.z * w.w;
            acc[3].x += a.w * w.x; acc[3].y += a.w * w.y; acc[3].z += a.w * w.z; acc[3].w += a.w * w.w;
        }
        __syncthreads();
    }

    int col = n0 + tc * 4;
    float4 bv = *(const float4*)&bias[col];
#pragma unroll
    for (int ri = 0; ri < 4; ri++) {
        int row = m0 + rg * 4 + ri;
        float4 v = acc[ri];
        v.x += bv.x; v.y += bv.y; v.z += bv.z; v.w += bv.w;
        if (mode == 0) {
            v.x = fmaxf(v.x, 0.f); v.y = fmaxf(v.y, 0.f);
            v.z = fmaxf(v.z, 0.f); v.w = fmaxf(v.w, 0.f);
        } else {
            v.x = sigmoidf_(v.x); v.y = sigmoidf_(v.y);
            v.z = sigmoidf_(v.z); v.w = sigmoidf_(v.w);
        }
        *(float4*)&Cout[row * ldc + col] = v;
    }
}

// ---------------- LSTM step ----------------
// gates[256,2048] = [x_t | h] @ [W_ih ; W_hh]  (K = 640), fused nonlinearity.
// Block tile: 64 batch rows x 16 j-cols x 4 gates (64 C-cols). Grid (32, 4) = 128 blocks.
// Each thread owns a 4x4 micro-tile whose 4 columns are the 4 gates of one j ->
// the cell/hidden update is thread-local.
__global__ __launch_bounds__(256) void lstm_step_kernel(
    const float* __restrict__ x,
    const float* __restrict__ W_ih, const float* __restrict__ W_hh,
    const float* __restrict__ b_ih, const float* __restrict__ b_hh,
    int t)
{
    const float* __restrict__ h_in = g_h[t & 1];
    float* __restrict__ h_out      = g_h[(t + 1) & 1];

    const int n0  = blockIdx.x * 16;   // j base
    const int bm0 = blockIdx.y * 64;   // batch base
    const int tid = threadIdx.x;
    const int tc = tid & 15;           // j offset within tile
    const int rg = tid >> 4;           // row group

    __shared__ float As[2][16][68];
    __shared__ float Ws[2][16][68];

    // per-thread load coordinates (4 A elems + 4 W elems per K-chunk)
    const int a_kk = tid & 15;                 // same for all u
    int a_r[4], w_kr[4], w_sc[4], w_gc[4];
#pragma unroll
    for (int u = 0; u < 4; u++) {
        int i = tid + u * 256;
        a_r[u]  = i >> 4;
        w_kr[u] = i >> 6;
        int c = i & 63;
        int g = c >> 4, jl = c & 15;
        w_sc[u] = jl * 4 + g;                  // smem col (gates interleaved)
        w_gc[u] = n0 + jl + g * 512;           // global W column
    }

    float4 acc[4];
#pragma unroll
    for (int i = 0; i < 4; i++) acc[i] = make_float4(0.f, 0.f, 0.f, 0.f);

    float a_reg[4], w_reg[4];

    // ---- preload chunk 0 ----
    {
        const int k0 = 0;
#pragma unroll
        for (int u = 0; u < 4; u++) {
            int k = k0 + a_kk;
            int b = bm0 + a_r[u];
            a_reg[u] = (k < Fsz) ? x[b * (Ssz * Fsz) + t * Fsz + k]
                                 : h_in[b * Hsz + (k - Fsz)];
            int kw = k0 + w_kr[u];
            w_reg[u] = (kw < Fsz) ? W_ih[kw * G4H + w_gc[u]]
                                  : W_hh[(kw - Fsz) * G4H + w_gc[u]];
        }
#pragma unroll
        for (int u = 0; u < 4; u++) {
            As[0][a_kk][a_r[u]]   = a_reg[u];
            Ws[0][w_kr[u]][w_sc[u]] = w_reg[u];
        }
    }
    __syncthreads();

    int buf = 0;
#pragma unroll 1
    for (int ch = 0; ch < 40; ch++) {
        if (ch < 39) {
            const int k0 = (ch + 1) * 16;
#pragma unroll
            for (int u = 0; u < 4; u++) {
                int k = k0 + a_kk;
                int b = bm0 + a_r[u];
                a_reg[u] = (k < Fsz) ? x[b * (Ssz * Fsz) + t * Fsz + k]
                                     : h_in[b * Hsz + (k - Fsz)];
                int kw = k0 + w_kr[u];
                w_reg[u] = (kw < Fsz) ? W_ih[kw * G4H + w_gc[u]]
                                      : W_hh[(kw - Fsz) * G4H + w_gc[u]];
            }
        }
#pragma unroll
        for (int kk = 0; kk < 16; kk++) {
            float4 w = *(const float4*)&Ws[buf][kk][tc * 4];
            float4 a = *(const float4*)&As[buf][kk][rg * 4];
            acc[0].x += a.x * w.x; acc[0].y += a.x * w.y; acc[0].z += a.x * w.z; acc[0].w += a.x * w.w;
            acc[1].x += a.y * w.x; acc[1].y += a.y * w.y; acc[1].z += a.y * w.z; acc[1].w += a.y * w.w;
            acc[2].x += a.z * w.x; acc[2].y += a.z * w.y; acc[2].z += a.z * w.z; acc[2].w += a.z * w.w;
            acc[3].x += a.w * w.x; acc[3].y += a.w * w.y; acc[3].z += a.w * w.z; acc[3].w += a.w * w.w;
        }
        if (ch < 39) {
            int nb = buf ^ 1;
#pragma unroll
            for (int u = 0; u < 4; u++) {
                As[nb][a_kk][a_r[u]]     = a_reg[u];
                Ws[nb][w_kr[u]][w_sc[u]] = w_reg[u];
            }
        }
        __syncthreads();
        buf ^= 1;
    }

    // ---- fused LSTM epilogue ----
    const int j = n0 + tc;
    const float bi = b_ih[j]        + b_hh[j];
    const float bf = b_ih[j + 512]  + b_hh[j + 512];
    const float bg = b_ih[j + 1024] + b_hh[j + 1024];
    const float bo = b_ih[j + 1536] + b_hh[j + 1536];

#pragma unroll
    for (int ri = 0; ri < 4; ri++) {
        int b = bm0 + rg * 4 + ri;
        int idx = b * Hsz + j;
        const float* ctx = &g_ctx[b * (3 * Hsz)];
        float iv = sigmoidf_(acc[ri].x + bi) * ctx[j];
        float fv = sigmoidf_(acc[ri].y + bf) * ctx[j + 512];
        float gv = tanhf(acc[ri].z + bg);
        float ov = sigmoidf_(acc[ri].w + bo) * ctx[j + 1024];
        float cn = fv * g_c[idx] + iv * gv;
        g_c[idx]   = cn;
        h_out[idx] = ov * tanhf(cn);
    }
}

// ---------------- mu / log_var / z ----------------
// one block per batch row, 512 threads (16 warps; warp w computes mu[l=w] & lv[l=w])
__global__ __launch_bounds__(512) void mulv_kernel(
    const float* __restrict__ mu_w, const float* __restrict__ mu_b,
    const float* __restrict__ lv_w, const float* __restrict__ lv_b,
    const float* __restrict__ eps, float* __restrict__ out)
{
    const int b = blockIdx.x;
    const int tid = threadIdx.x;
    __shared__ float sh[512];
    __shared__ float smu[16], slv[16];

    sh[tid] = g_h[0][b * Hsz + tid];   // final h lives in buffer 0 after 128 steps
    __syncthreads();

    const int w = tid >> 5, lane = tid & 31;
    const int l = w;  // 16 warps
    float sm = 0.f, sl = 0.f;
    for (int k = lane; k < Hsz; k += 32) {
        float hv = sh[k];
        sm += hv * mu_w[k * Lsz + l];
        sl += hv * lv_w[k * Lsz + l];
    }
#pragma unroll
    for (int o = 16; o > 0; o >>= 1) {
        sm += __shfl_down_sync(0xffffffffu, sm, o);
        sl += __shfl_down_sync(0xffffffffu, sl, o);
    }
    if (lane == 0) { smu[l] = sm; slv[l] = sl; }
    __syncthreads();

    if (tid < Lsz) {
        float mu = smu[tid] + mu_b[tid];
        float lv = slv[tid] + lv_b[tid];
        out[Bsz * Fsz + b * Lsz + tid] = mu;                 // mu block
        out[Bsz * Fsz + Bsz * Lsz + b * Lsz + tid] = lv;     // log_var block
        g_z[b * Lsz + tid] = mu + eps[b * Lsz + tid] * expf(0.5f * lv);
    }
}

// ---------------- decoder ----------------
// one block per batch row, 128 threads
__global__ __launch_bounds__(128) void dec_kernel(
    const float* __restrict__ dec_w1, const float* __restrict__ dec_b1,
    const float* __restrict__ dec_w2, const float* __restrict__ dec_b2,
    float* __restrict__ out)
{
    const int b = blockIdx.x;
    const int tid = threadIdx.x;
    __shared__ float sz[16];
    __shared__ float st[512];

    if (tid < 16) sz[tid] = g_z[b * Lsz + tid];
    __syncthreads();

#pragma unroll
    for (int u = 0; u < 4; u++) {
        int jj = tid + u * 128;
        float s = dec_b1[jj];
#pragma unroll
        for (int k = 0; k < 16; k++) s += sz[k] * dec_w1[k * Hsz + jj];
        st[jj] = fmaxf(s, 0.f);
    }
    __syncthreads();

    float r = dec_b2[tid];
    for (int k = 0; k < Hsz; k++) r += st[k] * dec_w2[k * Fsz + tid];
    out[b * Fsz + tid] = r;
}

// ---------------- launch ----------------
extern "C" void kernel_launch(void* const* d_in, const int* in_sizes, int n_in,
                              void* d_out, int out_size)
{
    const float* x       = (const float*)d_in[0];
    const float* context = (const float*)d_in[1];
    const float* eps     = (const float*)d_in[2];
    const float* W_ih    = (const float*)d_in[3];
    const float* b_ih    = (const float*)d_in[4];
    const float* W_hh    = (const float*)d_in[5];
    const float* b_hh    = (const float*)d_in[6];
    const float* cg_w1   = (const float*)d_in[7];
    const float* cg_b1   = (const float*)d_in[8];
    const float* cg_w2   = (const float*)d_in[9];
    const float* cg_b2   = (const float*)d_in[10];
    const float* mu_w    = (const float*)d_in[11];
    const float* mu_b    = (const float*)d_in[12];
    const float* lv_w    = (const float*)d_in[13];
    const float* lv_b    = (const float*)d_in[14];
    const float* dec_w1  = (const float*)d_in[15];
    const float* dec_b1  = (const float*)d_in[16];
    const float* dec_w2  = (const float*)d_in[17];
    const float* dec_b2  = (const float*)d_in[18];
    float* out = (float*)d_out;

    // zero h0, c
    init_kernel<<<(Bsz * Hsz + 511) / 512, 512>>>();

    // context gate (once; static across time)
    ctx_gemm_kernel<<<dim3(8, 4), 256>>>(context, cg_w1, cg_b1, 0);
    ctx_gemm_kernel<<<dim3(24, 4), 256>>>(nullptr, cg_w2, cg_b2, 1);

    // recurrence: 128 graph-captured step launches (kernel boundary = global sync)
    for (int t = 0; t < Ssz; t++) {
        lstm_step_kernel<<<dim3(32, 4), 256>>>(x, W_ih, W_hh, b_ih, b_hh, t);
    }

    // VAE head
    mulv_kernel<<<Bsz, 512>>>(mu_w, mu_b, lv_w, lv_b, eps, out);
    dec_kernel<<<Bsz, 128>>>(dec_w1, dec_b1, dec_w2, dec_b2, out);
}

// round 2
// speedup vs baseline: 1.1223x; 1.1223x over previous
#include <cuda_runtime.h>
#include <math.h>

#define Bsz 256
#define Ssz 128
#define Fsz 128
#define Hsz 512
#define G4H 2048
#define Csz 64
#define Lsz 16

typedef unsigned long long ull;

// ---------------- device scratch (no allocations allowed) ----------------
__device__ float g_h[2][Bsz * Hsz];     // double-buffered hidden state
__device__ float g_c[Bsz * Hsz];        // cell state (owner-exclusive per (b,j))
__device__ float g_ctx[Bsz * 3 * Hsz];  // sigmoid context gates [ci|cf|co] per row
__device__ float g_t1[Bsz * Hsz];       // relu(context@cg_w1+b)
__device__ float g_z[Bsz * Lsz];        // reparameterized latent

__device__ __forceinline__ float sigmoidf_(float v) { return 1.0f / (1.0f + expf(-v)); }

// packed fp32x2 FMA (FFMA2) — PTX-only, 2 MACs per issue slot
__device__ __forceinline__ ull fma2_(ull a, ull b, ull c) {
    ull d;
    asm("fma.rn.f32x2 %0, %1, %2, %3;" : "=l"(d) : "l"(a), "l"(b), "l"(c));
    return d;
}
__device__ __forceinline__ ull dup2_(float v) {
    unsigned int r = __float_as_uint(v);
    ull d;
    asm("mov.b64 %0, {%1, %1};" : "=l"(d) : "r"(r));
    return d;
}
__device__ __forceinline__ void unpack2_(ull v, float& lo, float& hi) {
    unsigned int a, b;
    asm("mov.b64 {%0, %1}, %2;" : "=r"(a), "=r"(b) : "l"(v));
    lo = __uint_as_float(a);
    hi = __uint_as_float(b);
}

// ---------------- init: zero h0 and c ----------------
__global__ void init_kernel() {
    int i = blockIdx.x * blockDim.x + threadIdx.x;
    if (i < Bsz * Hsz) { g_h[0][i] = 0.0f; g_c[i] = 0.0f; }
}

// ---------------- context-gate GEMMs ----------------
// mode 0: g_t1 = relu(context[256,64] @ cg_w1[64,512] + b)        grid (8,4)
// mode 1: g_ctx = sigmoid(g_t1[256,512] @ cg_w2[512,1536] + b)    grid (24,4)
__global__ __launch_bounds__(256) void ctx_gemm_kernel(
    const float* __restrict__ Aext, const float* __restrict__ W,
    const float* __restrict__ bias, int mode)
{
    const int K   = (mode == 0) ? 64 : 512;
    const int lda = (mode == 0) ? 64 : 512;
    const int ldw = (mode == 0) ? 512 : 1536;
    const int ldc = ldw;
    const float* A = (mode == 0) ? Aext : g_t1;
    float* Cout    = (mode == 0) ? g_t1 : g_ctx;

    const int n0 = blockIdx.x * 64;
    const int m0 = blockIdx.y * 64;
    const int tid = threadIdx.x;
    const int tc = tid & 15;
    const int rg = tid >> 4;

    __shared__ float As[16][68];
    __shared__ float Ws[16][68];

    float4 acc[4];
#pragma unroll
    for (int i = 0; i < 4; i++) acc[i] = make_float4(0.f, 0.f, 0.f, 0.f);

    for (int k0 = 0; k0 < K; k0 += 16) {
#pragma unroll
        for (int u = 0; u < 4; u++) {
            int i = tid + u * 256;
            int r = i >> 4, kk = i & 15;
            As[kk][r] = A[(m0 + r) * lda + k0 + kk];
            int kr = i >> 6, c = i & 63;
            Ws[kr][c] = W[(k0 + kr) * ldw + n0 + c];
        }
        __syncthreads();
#pragma unroll
        for (int kk = 0; kk < 16; kk++) {
            float4 w = *(const float4*)&Ws[kk][tc * 4];
            float4 a = *(const float4*)&As[kk][rg * 4];
            acc[0].x += a.x * w.x; acc[0].y += a.x * w.y; acc[0].z += a.x * w.z; acc[0].w += a.x * w.w;
            acc[1].x += a.y * w.x; acc[1].y += a.y * w.y; acc[1].z += a.y * w.z; acc[1].w += a.y * w.w;
            acc[2].x += a.z * w.x; acc[2].y += a.z * w.y; acc[2].z += a.z * w.z; acc[2].w += a.z * w.w;
            acc[3].x += a.w * w.x; acc[3].y += a.w * w.y; acc[3].z += a.w * w.z; acc[3].w += a.w * w.w;
        }
        __syncthreads();
    }

    int col = n0 + tc * 4;
    float4 bv = *(const float4*)&bias[col];
#pragma unroll
    for (int ri = 0; ri < 4; ri++) {
        int row = m0 + rg * 4 + ri;
        float4 v = acc[ri];
        v.x += bv.x; v.y += bv.y; v.z += bv.z; v.w += bv.w;
        if (mode == 0) {
            v.x = fmaxf(v.x, 0.f); v.y = fmaxf(v.y, 0.f);
            v.z = fmaxf(v.z, 0.f); v.w = fmaxf(v.w, 0.f);
        } else {
            v.x = sigmoidf_(v.x); v.y = sigmoidf_(v.y);
            v.z = sigmoidf_(v.z); v.w = sigmoidf_(v.w);
        }
        *(float4*)&Cout[row * ldc + col] = v;
    }
}

// ---------------- LSTM step (FFMA2 version) ----------------
// gates[256,2048] = [x_t | h] @ [W_ih ; W_hh]  (K = 640), fused nonlinearity.
// Tile: 64 batch x 16 j x 4 gates. Grid (32,4) = 128 blocks x 256 threads.
// Micro-tile 4 rows x 4 gates per thread; gate quad packed into 2 f32x2 accumulators.
// K-chunk = 32 (20 chunks -> 20 barriers), double-buffered smem.
__global__ __launch_bounds__(256) void lstm_step_kernel(
    const float* __restrict__ x,
    const float* __restrict__ W_ih, const float* __restrict__ W_hh,
    const float* __restrict__ b_ih, const float* __restrict__ b_hh,
    int t)
{
    const float* __restrict__ h_in = g_h[t & 1];
    float* __restrict__ h_out      = g_h[(t + 1) & 1];

    const int n0  = blockIdx.x * 16;   // j base
    const int bm0 = blockIdx.y * 64;   // batch base
    const int tid = threadIdx.x;
    const int tc = tid & 15;           // j offset within tile
    const int rg = tid >> 4;           // row group (rows rg*4..rg*4+3)

    __shared__ float As[2][32][68];
    __shared__ float Ws[2][32][68];

    // per-thread load coordinates (8 A elems + 8 W elems per 32-deep K-chunk)
    const int akk  = tid & 31;          // A smem k-row (const across u)
    const int ar0  = tid >> 5;          // A row base; rows ar0 + u*8
    const int wc   = tid & 63;          // W col id (const across u)
    const int wg   = wc >> 4;           // gate index 0..3
    const int wjl  = wc & 15;           // local j
    const int wsc  = wjl * 4 + wg;      // smem col (gates interleaved)
    const int wgc  = n0 + wjl + wg * 512; // global W column
    const int wkr0 = tid >> 6;          // W k-row base; rows wkr0 + u*4

    float a_reg[8], w_reg[8];

    // ---- preload chunk 0 ----
#pragma unroll
    for (int u = 0; u < 8; u++) {
        int k = akk;                      // k0 = 0
        int b = bm0 + ar0 + u * 8;
        a_reg[u] = (k < Fsz) ? x[b * (Ssz * Fsz) + t * Fsz + k]
                             : h_in[b * Hsz + (k - Fsz)];
        int kw = wkr0 + u * 4;
        w_reg[u] = (kw < Fsz) ? W_ih[kw * G4H + wgc]
                              : W_hh[(kw - Fsz) * G4H + wgc];
    }
#pragma unroll
    for (int u = 0; u < 8; u++) {
        As[0][akk][ar0 + u * 8]     = a_reg[u];
        Ws[0][wkr0 + u * 4][wsc]    = w_reg[u];
    }
    __syncthreads();

    ull acc01[4] = {0ull, 0ull, 0ull, 0ull};   // (gate i, gate f) per row
    ull acc23[4] = {0ull, 0ull, 0ull, 0ull};   // (gate g, gate o) per row

    int buf = 0;
#pragma unroll 1
    for (int ch = 0; ch < 20; ch++) {
        if (ch < 19) {
            const int k0 = (ch + 1) * 32;
#pragma unroll
            for (int u = 0; u < 8; u++) {
                int k = k0 + akk;
                int b = bm0 + ar0 + u * 8;
                a_reg[u] = (k < Fsz) ? x[b * (Ssz * Fsz) + t * Fsz + k]
                                     : h_in[b * Hsz + (k - Fsz)];
                int kw = k0 + wkr0 + u * 4;
                w_reg[u] = (kw < Fsz) ? W_ih[kw * G4H + wgc]
                                      : W_hh[(kw - Fsz) * G4H + wgc];
            }
        }
#pragma unroll
        for (int kk = 0; kk < 32; kk++) {
            float4 a = *(const float4*)&As[buf][kk][rg * 4];
            const ull* wv = (const ull*)&Ws[buf][kk][tc * 4];
            ull w01 = wv[0];
            ull w23 = wv[1];
            ull d;
            d = dup2_(a.x); acc01[0] = fma2_(d, w01, acc01[0]); acc23[0] = fma2_(d, w23, acc23[0]);
            d = dup2_(a.y); acc01[1] = fma2_(d, w01, acc01[1]); acc23[1] = fma2_(d, w23, acc23[1]);
            d = dup2_(a.z); acc01[2] = fma2_(d, w01, acc01[2]); acc23[2] = fma2_(d, w23, acc23[2]);
            d = dup2_(a.w); acc01[3] = fma2_(d, w01, acc01[3]); acc23[3] = fma2_(d, w23, acc23[3]);
        }
        if (ch < 19) {
            int nb = buf ^ 1;
#pragma unroll
            for (int u = 0; u < 8; u++) {
                As[nb][akk][ar0 + u * 8]  = a_reg[u];
                Ws[nb][wkr0 + u * 4][wsc] = w_reg[u];
            }
        }
        __syncthreads();
        buf ^= 1;
    }

    // ---- fused LSTM epilogue ----
    const int j = n0 + tc;
    const float bi = b_ih[j]        + b_hh[j];
    const float bf = b_ih[j + 512]  + b_hh[j + 512];
    const float bg = b_ih[j + 1024] + b_hh[j + 1024];
    const float bo = b_ih[j + 1536] + b_hh[j + 1536];

#pragma unroll
    for (int ri = 0; ri < 4; ri++) {
        int b = bm0 + rg * 4 + ri;
        int idx = b * Hsz + j;
        const float* ctx = &g_ctx[b * (3 * Hsz)];
        float si, sf, sg, so;
        unpack2_(acc01[ri], si, sf);
        unpack2_(acc23[ri], sg, so);
        float iv = sigmoidf_(si + bi) * ctx[j];
        float fv = sigmoidf_(sf + bf) * ctx[j + 512];
        float gv = tanhf(sg + bg);
        float ov = sigmoidf_(so + bo) * ctx[j + 1024];
        float cn = fv * g_c[idx] + iv * gv;
        g_c[idx]   = cn;
        h_out[idx] = ov * tanhf(cn);
    }
}

// ---------------- mu / log_var / z ----------------
__global__ __launch_bounds__(512) void mulv_kernel(
    const float* __restrict__ mu_w, const float* __restrict__ mu_b,
    const float* __restrict__ lv_w, const float* __restrict__ lv_b,
    const float* __restrict__ eps, float* __restrict__ out)
{
    const int b = blockIdx.x;
    const int tid = threadIdx.x;
    __shared__ float sh[512];
    __shared__ float smu[16], slv[16];

    sh[tid] = g_h[0][b * Hsz + tid];   // final h lives in buffer 0 after 128 steps
    __syncthreads();

    const int w = tid >> 5, lane = tid & 31;
    const int l = w;  // 16 warps
    float sm = 0.f, sl = 0.f;
    for (int k = lane; k < Hsz; k += 32) {
        float hv = sh[k];
        sm += hv * mu_w[k * Lsz + l];
        sl += hv * lv_w[k * Lsz + l];
    }
#pragma unroll
    for (int o = 16; o > 0; o >>= 1) {
        sm += __shfl_down_sync(0xffffffffu, sm, o);
        sl += __shfl_down_sync(0xffffffffu, sl, o);
    }
    if (lane == 0) { smu[l] = sm; slv[l] = sl; }
    __syncthreads();

    if (tid < Lsz) {
        float mu = smu[tid] + mu_b[tid];
        float lv = slv[tid] + lv_b[tid];
        out[Bsz * Fsz + b * Lsz + tid] = mu;                 // mu block
        out[Bsz * Fsz + Bsz * Lsz + b * Lsz + tid] = lv;     // log_var block
        g_z[b * Lsz + tid] = mu + eps[b * Lsz + tid] * expf(0.5f * lv);
    }
}

// ---------------- decoder ----------------
__global__ __launch_bounds__(128) void dec_kernel(
    const float* __restrict__ dec_w1, const float* __restrict__ dec_b1,
    const float* __restrict__ dec_w2, const float* __restrict__ dec_b2,
    float* __restrict__ out)
{
    const int b = blockIdx.x;
    const int tid = threadIdx.x;
    __shared__ float sz[16];
    __shared__ float st[512];

    if (tid < 16) sz[tid] = g_z[b * Lsz + tid];
    __syncthreads();

#pragma unroll
    for (int u = 0; u < 4; u++) {
        int jj = tid + u * 128;
        float s = dec_b1[jj];
#pragma unroll
        for (int k = 0; k < 16; k++) s += sz[k] * dec_w1[k * Hsz + jj];
        st[jj] = fmaxf(s, 0.f);
    }
    __syncthreads();

    float r = dec_b2[tid];
    for (int k = 0; k < Hsz; k++) r += st[k] * dec_w2[k * Fsz + tid];
    out[b * Fsz + tid] = r;
}

// ---------------- launch ----------------
extern "C" void kernel_launch(void* const* d_in, const int* in_sizes, int n_in,
                              void* d_out, int out_size)
{
    const float* x       = (const float*)d_in[0];
    const float* context = (const float*)d_in[1];
    const float* eps     = (const float*)d_in[2];
    const float* W_ih    = (const float*)d_in[3];
    const float* b_ih    = (const float*)d_in[4];
    const float* W_hh    = (const float*)d_in[5];
    const float* b_hh    = (const float*)d_in[6];
    const float* cg_w1   = (const float*)d_in[7];
    const float* cg_b1   = (const float*)d_in[8];
    const float* cg_w2   = (const float*)d_in[9];
    const float* cg_b2   = (const float*)d_in[10];
    const float* mu_w    = (const float*)d_in[11];
    const float* mu_b    = (const float*)d_in[12];
    const float* lv_w    = (const float*)d_in[13];
    const float* lv_b    = (const float*)d_in[14];
    const float* dec_w1  = (const float*)d_in[15];
    const float* dec_b1  = (const float*)d_in[16];
    const float* dec_w2  = (const float*)d_in[17];
    const float* dec_b2  = (const float*)d_in[18];
    float* out = (float*)d_out;

    // zero h0, c
    init_kernel<<<(Bsz * Hsz + 511) / 512, 512>>>();

    // context gate (once; static across time)
    ctx_gemm_kernel<<<dim3(8, 4), 256>>>(context, cg_w1, cg_b1, 0);
    ctx_gemm_kernel<<<dim3(24, 4), 256>>>(nullptr, cg_w2, cg_b2, 1);

    // recurrence: 128 graph-captured step launches (kernel boundary = global sync)
    for (int t = 0; t < Ssz; t++) {
        lstm_step_kernel<<<dim3(32, 4), 256>>>(x, W_ih, W_hh, b_ih, b_hh, t);
    }

    // VAE head
    mulv_kernel<<<Bsz, 512>>>(mu_w, mu_b, lv_w, lv_b, eps, out);
    dec_kernel<<<Bsz, 128>>>(dec_w1, dec_b1, dec_w2, dec_b2, out);
}

// round 4
// speedup vs baseline: 2.0561x; 1.8320x over previous
#include <cuda_runtime.h>
#include <cuda_bf16.h>
#include <math.h>
#include <stdint.h>

#define Bsz 256
#define Ssz 128
#define Fsz 128
#define Hsz 512
#define G4H 2048
#define Csz 64
#define Lsz 16
#define NCH 20            // K=640 in k32 chunks

// ---------------- device scratch ----------------
__device__ float g_h[2][Bsz * Hsz];
__device__ float g_c[Bsz * Hsz];
__device__ float g_ctx[Bsz * 3 * Hsz];
__device__ float g_t1[Bsz * Hsz];
__device__ float g_z[Bsz * Lsz];
// split-bf16 operands. W: [n][640], n = j*4 + gate (gate-interleaved cols)
__device__ __nv_bfloat16 g_wh[2048 * 640];
__device__ __nv_bfloat16 g_wl[2048 * 640];
__device__ __nv_bfloat16 g_xh[Bsz * Ssz * Fsz];
__device__ __nv_bfloat16 g_xl[Bsz * Ssz * Fsz];
__device__ __nv_bfloat16 g_hh[2][Bsz * Hsz];
__device__ __nv_bfloat16 g_hl[2][Bsz * Hsz];

__device__ __forceinline__ float sigmoidf_(float v) { return 1.0f / (1.0f + expf(-v)); }

__device__ __forceinline__ uint32_t smem_to_u32(const void* p) {
    uint32_t a;
    asm("{ .reg .u64 t; cvta.to.shared.u64 t, %1; cvt.u32.u64 %0, t; }" : "=r"(a) : "l"(p));
    return a;
}
__device__ __forceinline__ void cp16(uint32_t dst, const void* src) {
    asm volatile("cp.async.cg.shared.global [%0], [%1], 16;" :: "r"(dst), "l"(src));
}
#define CP_COMMIT() asm volatile("cp.async.commit_group;" ::: "memory")
#define CP_WAIT(n)  asm volatile("cp.async.wait_group %0;" :: "n"(n) : "memory")

#define LDSM4(r0, r1, r2, r3, a) \
    asm volatile("ldmatrix.sync.aligned.m8n8.x4.shared.b16 {%0,%1,%2,%3}, [%4];" \
                 : "=r"(r0), "=r"(r1), "=r"(r2), "=r"(r3) : "r"(a))

#define MMA(c, a0, a1, a2, a3, b0, b1) \
    asm volatile("mma.sync.aligned.m16n8k16.row.col.f32.bf16.bf16.f32 " \
                 "{%0,%1,%2,%3}, {%4,%5,%6,%7}, {%8,%9}, {%0,%1,%2,%3};" \
                 : "+f"((c)[0]), "+f"((c)[1]), "+f"((c)[2]), "+f"((c)[3]) \
                 : "r"(a0), "r"(a1), "r"(a2), "r"(a3), "r"(b0), "r"(b1))

__device__ __forceinline__ void bsplit(float v, unsigned short& h, unsigned short& l) {
    __nv_bfloat16 bh = __float2bfloat16(v);
    float r = v - __bfloat162float(bh);
    __nv_bfloat16 bl = __float2bfloat16(r);
    h = *(unsigned short*)&bh;
    l = *(unsigned short*)&bl;
}

// ---------------- init: zero h0, c, bf16 h0 ----------------
__global__ void init_kernel() {
    int i = blockIdx.x * blockDim.x + threadIdx.x;
    if (i < Bsz * Hsz) {
        g_h[0][i] = 0.0f; g_c[i] = 0.0f;
        g_hh[0][i] = __float2bfloat16(0.f);
        g_hl[0][i] = __float2bfloat16(0.f);
    }
}

// ---------------- W split: [k][2048] fp32 -> [n][640] bf16 hi/lo ----------------
__global__ __launch_bounds__(128) void wsplit_kernel(
    const float* __restrict__ W_ih, const float* __restrict__ W_hh)
{
    const int n = blockIdx.x;             // 0..2047
    const int j = n >> 2, g = n & 3;
    const int col = g * Hsz + j;
    for (int k = threadIdx.x; k < 640; k += 128) {
        float v = (k < Fsz) ? W_ih[k * G4H + col] : W_hh[(k - Fsz) * G4H + col];
        unsigned short h, l;
        bsplit(v, h, l);
        ((unsigned short*)g_wh)[n * 640 + k] = h;
        ((unsigned short*)g_wl)[n * 640 + k] = l;
    }
}

// ---------------- x split ----------------
__global__ __launch_bounds__(256) void xsplit_kernel(const float* __restrict__ x) {
    int i4 = blockIdx.x * blockDim.x + threadIdx.x;     // 4 elements per thread
    float4 v = *(const float4*)(x + (size_t)i4 * 4);
    unsigned short h[4], l[4];
    bsplit(v.x, h[0], l[0]); bsplit(v.y, h[1], l[1]);
    bsplit(v.z, h[2], l[2]); bsplit(v.w, h[3], l[3]);
    uint2 hp, lp;
    hp.x = (uint32_t)h[0] | ((uint32_t)h[1] << 16);
    hp.y = (uint32_t)h[2] | ((uint32_t)h[3] << 16);
    lp.x = (uint32_t)l[0] | ((uint32_t)l[1] << 16);
    lp.y = (uint32_t)l[2] | ((uint32_t)l[3] << 16);
    *(uint2*)((unsigned short*)g_xh + (size_t)i4 * 4) = hp;
    *(uint2*)((unsigned short*)g_xl + (size_t)i4 * 4) = lp;
}

// ---------------- context-gate GEMMs (tiny, unchanged) ----------------
__global__ __launch_bounds__(256) void ctx_gemm_kernel(
    const float* __restrict__ Aext, const float* __restrict__ W,
    const float* __restrict__ bias, int mode)
{
    const int K   = (mode == 0) ? 64 : 512;
    const int lda = (mode == 0) ? 64 : 512;
    const int ldw = (mode == 0) ? 512 : 1536;
    const int ldc = ldw;
    const float* A = (mode == 0) ? Aext : g_t1;
    float* Cout    = (mode == 0) ? g_t1 : g_ctx;

    const int n0 = blockIdx.x * 64;
    const int m0 = blockIdx.y * 64;
    const int tid = threadIdx.x;
    const int tc = tid & 15;
    const int rg = tid >> 4;

    __shared__ float As[16][68];
    __shared__ float Ws[16][68];

    float4 acc[4];
#pragma unroll
    for (int i = 0; i < 4; i++) acc[i] = make_float4(0.f, 0.f, 0.f, 0.f);

    for (int k0 = 0; k0 < K; k0 += 16) {
#pragma unroll
        for (int u = 0; u < 4; u++) {
            int i = tid + u * 256;
            int r = i >> 4, kk = i & 15;
            As[kk][r] = A[(m0 + r) * lda + k0 + kk];
            int kr = i >> 6, c = i & 63;
            Ws[kr][c] = W[(k0 + kr) * ldw + n0 + c];
        }
        __syncthreads();
#pragma unroll
        for (int kk = 0; kk < 16; kk++) {
            float4 w = *(const float4*)&Ws[kk][tc * 4];
            float4 a = *(const float4*)&As[kk][rg * 4];
            acc[0].x += a.x * w.x; acc[0].y += a.x * w.y; acc[0].z += a.x * w.z; acc[0].w += a.x * w.w;
            acc[1].x += a.y * w.x; acc[1].y += a.y * w.y; acc[1].z += a.y * w.z; acc[1].w += a.y * w.w;
            acc[2].x += a.z * w.x; acc[2].y += a.z * w.y; acc[2].z += a.z * w.z; acc[2].w += a.z * w.w;
            acc[3].x += a.w * w.x; acc[3].y += a.w * w.y; acc[3].z += a.w * w.z; acc[3].w += a.w * w.w;
        }
        __syncthreads();
    }

    int col = n0 + tc * 4;
    float4 bv = *(const float4*)&bias[col];
#pragma unroll
    for (int ri = 0; ri < 4; ri++) {
        int row = m0 + rg * 4 + ri;
        float4 v = acc[ri];
        v.x += bv.x; v.y += bv.y; v.z += bv.z; v.w += bv.w;
        if (mode == 0) {
            v.x = fmaxf(v.x, 0.f); v.y = fmaxf(v.y, 0.f);
            v.z = fmaxf(v.z, 0.f); v.w = fmaxf(v.w, 0.f);
        } else {
            v.x = sigmoidf_(v.x); v.y = sigmoidf_(v.y);
            v.z = sigmoidf_(v.z); v.w = sigmoidf_(v.w);
        }
        *(float4*)&Cout[row * ldc + col] = v;
    }
}

// ---------------- LSTM step: mma.sync (HMMA) split-bf16 3-pass ----------------
// grid (32,4): bx = 64 interleaved gate-cols (16 j), by = 64 batch rows. 256 thr = 8 warps (4m x 2n).
// 3-stage smem pipeline; stage = Ahi|Alo|Whi|Wlo, each 4KB = [kb:2][64 rows][32B swizzled].
__global__ __launch_bounds__(256, 1) void lstm_step_mma(
    const float* __restrict__ b_ih, const float* __restrict__ b_hh, int t)
{
    __shared__ __align__(1024) char smbuf[49152];
    const uint32_t sb = smem_to_u32(smbuf);
    const int tid = threadIdx.x;
    const int lane = tid & 31, wid = tid >> 5;
    const int n0 = blockIdx.x * 64, j0 = blockIdx.x * 16;
    const int m0 = blockIdx.y * 64;
    const int par = t & 1;

    const int m0w = (wid >> 1) * 16;
    const int n0w = (wid & 1) * 32;
    // ldmatrix per-lane source offsets (32B rows, 16B-segment XOR swizzle)
    const int rA = m0w + (lane & 15);
    const uint32_t offA = rA * 32 + ((((lane >> 4) ^ (rA >> 2)) & 1) << 4);
    const int rB = n0w + ((lane >> 4) << 3) + (lane & 7);
    const uint32_t offB = rB * 32 + ((((lane >> 3) ^ (rB >> 2)) & 1) << 4);

    // cp.async fill coords: thread -> (row = tid>>2, 16B k-segment s4 = tid&3)
    const int cr = tid >> 2;
    const int s4 = tid & 3;
    const uint32_t adst = (s4 >> 1) * 2048 + cr * 32 + (((s4 ^ (cr >> 2)) & 1) << 4);

    const __nv_bfloat16* hh = g_hh[par];
    const __nv_bfloat16* hl = g_hl[par];

    float acc[4][4];
#pragma unroll
    for (int i = 0; i < 4; i++)
#pragma unroll
        for (int q = 0; q < 4; q++) acc[i][q] = 0.f;

    auto fill = [&](int cc) {
        const uint32_t st = sb + (cc % 3) * 16384;
        const int ck = cc * 32;
        size_t aoff;
        const __nv_bfloat16 *ah, *al;
        if (cc < 4) {
            ah = g_xh; al = g_xl;
            aoff = (size_t)(m0 + cr) * (Ssz * Fsz) + (size_t)t * Fsz + ck + s4 * 8;
        } else {
            ah = hh; al = hl;
            aoff = (size_t)(m0 + cr) * Hsz + (ck - Fsz) + s4 * 8;
        }
        cp16(st + adst,         ah + aoff);
        cp16(st + 4096 + adst,  al + aoff);
        const size_t woff = (size_t)(n0 + cr) * 640 + ck + s4 * 8;
        cp16(st + 8192 + adst,  g_wh + woff);
        cp16(st + 12288 + adst, g_wl + woff);
    };

    fill(0); CP_COMMIT();
    fill(1); CP_COMMIT();

#pragma unroll 1
    for (int c = 0; c < NCH; c++) {
        if (c < NCH - 1) { CP_WAIT(1); } else { CP_WAIT(0); }
        __syncthreads();
        if (c + 2 < NCH) fill(c + 2);
        CP_COMMIT();

        const uint32_t st = sb + (c % 3) * 16384;
#pragma unroll
        for (int kb = 0; kb < 2; kb++) {
            const uint32_t base = st + kb * 2048;
            uint32_t a0, a1, a2, a3, l0, l1, l2, l3;
            LDSM4(a0, a1, a2, a3, base + offA);
            LDSM4(l0, l1, l2, l3, base + 4096 + offA);
            uint32_t bh0, bh1, bh2, bh3, bh4, bh5, bh6, bh7;
            LDSM4(bh0, bh1, bh2, bh3, base + 8192 + offB);
            LDSM4(bh4, bh5, bh6, bh7, base + 8192 + offB + 512);
            uint32_t bl0, bl1, bl2, bl3, bl4, bl5, bl6, bl7;
            LDSM4(bl0, bl1, bl2, bl3, base + 12288 + offB);
            LDSM4(bl4, bl5, bl6, bl7, base + 12288 + offB + 512);

            MMA(acc[0], a0, a1, a2, a3, bh0, bh1);
            MMA(acc[1], a0, a1, a2, a3, bh2, bh3);
            MMA(acc[2], a0, a1, a2, a3, bh4, bh5);
            MMA(acc[3], a0, a1, a2, a3, bh6, bh7);
            MMA(acc[0], l0, l1, l2, l3, bh0, bh1);
            MMA(acc[1], l0, l1, l2, l3, bh2, bh3);
            MMA(acc[2], l0, l1, l2, l3, bh4, bh5);
            MMA(acc[3], l0, l1, l2, l3, bh6, bh7);
            MMA(acc[0], a0, a1, a2, a3, bl0, bl1);
            MMA(acc[1], a0, a1, a2, a3, bl2, bl3);
            MMA(acc[2], a0, a1, a2, a3, bl4, bl5);
            MMA(acc[3], a0, a1, a2, a3, bl6, bl7);
        }
    }

    // ---- C to smem (reuse stage0), then fused LSTM epilogue ----
    float* Cs = (float*)smbuf;
#pragma unroll
    for (int nt = 0; nt < 4; nt++) {
        const int colb = n0w + nt * 8 + (lane & 3) * 2;
        const int row = m0w + (lane >> 2);
        Cs[row * 64 + colb]           = acc[nt][0];
        Cs[row * 64 + colb + 1]       = acc[nt][1];
        Cs[(row + 8) * 64 + colb]     = acc[nt][2];
        Cs[(row + 8) * 64 + colb + 1] = acc[nt][3];
    }
    __syncthreads();

    const int jl = tid & 15, rg = tid >> 4;
    const int j = j0 + jl;
    const float bi  = b_ih[j]        + b_hh[j];
    const float bff = b_ih[j + 512]  + b_hh[j + 512];
    const float bg  = b_ih[j + 1024] + b_hh[j + 1024];
    const float bo  = b_ih[j + 1536] + b_hh[j + 1536];
    float* h_out = g_h[(t + 1) & 1];
    __nv_bfloat16* hho = g_hh[(t + 1) & 1];
    __nv_bfloat16* hlo = g_hl[(t + 1) & 1];

#pragma unroll
    for (int ri = 0; ri < 4; ri++) {
        const int row = rg * 4 + ri;
        const int b = m0 + row;
        float4 gv = *(float4*)&Cs[row * 64 + jl * 4];
        const float* ctx = &g_ctx[(size_t)b * (3 * Hsz)];
        float iv = sigmoidf_(gv.x + bi)  * ctx[j];
        float fv = sigmoidf_(gv.y + bff) * ctx[j + 512];
        float gg = tanhf(gv.z + bg);
        float ov = sigmoidf_(gv.w + bo)  * ctx[j + 1024];
        const int idx = b * Hsz + j;
        float cn = fv * g_c[idx] + iv * gg;
        g_c[idx] = cn;
        float hn = ov * tanhf(cn);
        h_out[idx] = hn;
        __nv_bfloat16 hb = __float2bfloat16(hn);
        hho[idx] = hb;
        hlo[idx] = __float2bfloat16(hn - __bfloat162float(hb));
    }
}

// ---------------- mu / log_var / z ----------------
__global__ __launch_bounds__(512) void mulv_kernel(
    const float* __restrict__ mu_w, const float* __restrict__ mu_b,
    const float* __restrict__ lv_w, const float* __restrict__ lv_b,
    const float* __restrict__ eps, float* __restrict__ out)
{
    const int b = blockIdx.x;
    const int tid = threadIdx.x;
    __shared__ float sh[512];
    __shared__ float smu[16], slv[16];

    sh[tid] = g_h[0][b * Hsz + tid];
    __syncthreads();

    const int w = tid >> 5, lane = tid & 31;
    const int l = w;
    float sm = 0.f, sl = 0.f;
    for (int k = lane; k < Hsz; k += 32) {
        float hv = sh[k];
        sm += hv * mu_w[k * Lsz + l];
        sl += hv * lv_w[k * Lsz + l];
    }
#pragma unroll
    for (int o = 16; o > 0; o >>= 1) {
        sm += __shfl_down_sync(0xffffffffu, sm, o);
        sl += __shfl_down_sync(0xffffffffu, sl, o);
    }
    if (lane == 0) { smu[l] = sm; slv[l] = sl; }
    __syncthreads();

    if (tid < Lsz) {
        float mu = smu[tid] + mu_b[tid];
        float lv = slv[tid] + lv_b[tid];
        out[Bsz * Fsz + b * Lsz + tid] = mu;
        out[Bsz * Fsz + Bsz * Lsz + b * Lsz + tid] = lv;
        g_z[b * Lsz + tid] = mu + eps[b * Lsz + tid] * expf(0.5f * lv);
    }
}

// ---------------- decoder ----------------
__global__ __launch_bounds__(128) void dec_kernel(
    const float* __restrict__ dec_w1, const float* __restrict__ dec_b1,
    const float* __restrict__ dec_w2, const float* __restrict__ dec_b2,
    float* __restrict__ out)
{
    const int b = blockIdx.x;
    const int tid = threadIdx.x;
    __shared__ float sz[16];
    __shared__ float st[512];

    if (tid < 16) sz[tid] = g_z[b * Lsz + tid];
    __syncthreads();

#pragma unroll
    for (int u = 0; u < 4; u++) {
        int jj = tid + u * 128;
        float s = dec_b1[jj];
#pragma unroll
        for (int k = 0; k < 16; k++) s += sz[k] * dec_w1[k * Hsz + jj];
        st[jj] = fmaxf(s, 0.f);
    }
    __syncthreads();

    float r = dec_b2[tid];
    for (int k = 0; k < Hsz; k++) r += st[k] * dec_w2[k * Fsz + tid];
    out[b * Fsz + tid] = r;
}

// ---------------- launch ----------------
extern "C" void kernel_launch(void* const* d_in, const int* in_sizes, int n_in,
                              void* d_out, int out_size)
{
    const float* x       = (const float*)d_in[0];
    const float* context = (const float*)d_in[1];
    const float* eps     = (const float*)d_in[2];
    const float* W_ih    = (const float*)d_in[3];
    const float* b_ih    = (const float*)d_in[4];
    const float* W_hh    = (const float*)d_in[5];
    const float* b_hh    = (const float*)d_in[6];
    const float* cg_w1   = (const float*)d_in[7];
    const float* cg_b1   = (const float*)d_in[8];
    const float* cg_w2   = (const float*)d_in[9];
    const float* cg_b2   = (const float*)d_in[10];
    const float* mu_w    = (const float*)d_in[11];
    const float* mu_b    = (const float*)d_in[12];
    const float* lv_w    = (const float*)d_in[13];
    const float* lv_b    = (const float*)d_in[14];
    const float* dec_w1  = (const float*)d_in[15];
    const float* dec_b1  = (const float*)d_in[16];
    const float* dec_w2  = (const float*)d_in[17];
    const float* dec_b2  = (const float*)d_in[18];
    float* out = (float*)d_out;

    init_kernel<<<(Bsz * Hsz + 511) / 512, 512>>>();
    wsplit_kernel<<<2048, 128>>>(W_ih, W_hh);
    xsplit_kernel<<<(Bsz * Ssz * Fsz) / (256 * 4), 256>>>(x);

    ctx_gemm_kernel<<<dim3(8, 4), 256>>>(context, cg_w1, cg_b1, 0);
    ctx_gemm_kernel<<<dim3(24, 4), 256>>>(nullptr, cg_w2, cg_b2, 1);

    for (int t = 0; t < Ssz; t++) {
        lstm_step_mma<<<dim3(32, 4), 256>>>(b_ih, b_hh, t);
    }

    mulv_kernel<<<Bsz, 512>>>(mu_w, mu_b, lv_w, lv_b, eps, out);
    dec_kernel<<<Bsz, 128>>>(dec_w1, dec_b1, dec_w2, dec_b2, out);
}

// round 5
// speedup vs baseline: 2.6931x; 1.3098x over previous
#include <cuda_runtime.h>
#include <cuda_bf16.h>
#include <math.h>
#include <stdint.h>

#define Bsz 256
#define Ssz 128
#define Fsz 128
#define Hsz 512
#define G4H 2048
#define Csz 64
#define Lsz 16
#define NCH 20            // K=640 in k32 chunks

// smem layout of persistent kernel
#define WHI_OFF 0         // resident W hi: 20 chunks x 4096B
#define WLO_OFF 81920     // resident W lo
#define ABASE   163840    // 3 A stages x 8192B (hi 4KB + lo 4KB); also C epilogue (16KB)
#define SMEM_PERSIST (ABASE + 3 * 8192)   // 188416

// ---------------- device scratch ----------------
__device__ float g_h[2][Bsz * Hsz];     // only [0] used (final h for mulv)
__device__ float g_c[Bsz * Hsz];        // unused by persistent path (kept for layout)
__device__ float g_ctx[Bsz * 3 * Hsz];
__device__ float g_t1[Bsz * Hsz];
__device__ float g_z[Bsz * Lsz];
__device__ unsigned int g_bar;
// split-bf16 operands. W: [n][640], n = j*4 + gate (gate-interleaved cols)
__device__ __nv_bfloat16 g_wh[2048 * 640];
__device__ __nv_bfloat16 g_wl[2048 * 640];
__device__ __nv_bfloat16 g_xh[Bsz * Ssz * Fsz];
__device__ __nv_bfloat16 g_xl[Bsz * Ssz * Fsz];
__device__ __nv_bfloat16 g_hh[2][Bsz * Hsz];
__device__ __nv_bfloat16 g_hl[2][Bsz * Hsz];

__device__ __forceinline__ float sigmoidf_(float v) { return 1.0f / (1.0f + expf(-v)); }

__device__ __forceinline__ uint32_t smem_to_u32(const void* p) {
    uint32_t a;
    asm("{ .reg .u64 t; cvta.to.shared.u64 t, %1; cvt.u32.u64 %0, t; }" : "=r"(a) : "l"(p));
    return a;
}
__device__ __forceinline__ void cp16(uint32_t dst, const void* src) {
    asm volatile("cp.async.cg.shared.global [%0], [%1], 16;" :: "r"(dst), "l"(src));
}
#define CP_COMMIT() asm volatile("cp.async.commit_group;" ::: "memory")
#define CP_WAIT(n)  asm volatile("cp.async.wait_group %0;" :: "n"(n) : "memory")

#define LDSM4(r0, r1, r2, r3, a) \
    asm volatile("ldmatrix.sync.aligned.m8n8.x4.shared.b16 {%0,%1,%2,%3}, [%4];" \
                 : "=r"(r0), "=r"(r1), "=r"(r2), "=r"(r3) : "r"(a))

#define MMA(c, a0, a1, a2, a3, b0, b1) \
    asm volatile("mma.sync.aligned.m16n8k16.row.col.f32.bf16.bf16.f32 " \
                 "{%0,%1,%2,%3}, {%4,%5,%6,%7}, {%8,%9}, {%0,%1,%2,%3};" \
                 : "+f"((c)[0]), "+f"((c)[1]), "+f"((c)[2]), "+f"((c)[3]) \
                 : "r"(a0), "r"(a1), "r"(a2), "r"(a3), "r"(b0), "r"(b1))

__device__ __forceinline__ void bsplit(float v, unsigned short& h, unsigned short& l) {
    __nv_bfloat16 bh = __float2bfloat16(v);
    float r = v - __bfloat162float(bh);
    __nv_bfloat16 bl = __float2bfloat16(r);
    h = *(unsigned short*)&bh;
    l = *(unsigned short*)&bl;
}

// ---------------- init ----------------
__global__ void init_kernel() {
    int i = blockIdx.x * blockDim.x + threadIdx.x;
    if (i == 0) g_bar = 0u;
    if (i < Bsz * Hsz) {
        g_hh[0][i] = __float2bfloat16(0.f);
        g_hl[0][i] = __float2bfloat16(0.f);
    }
}

// ---------------- W split: [k][2048] fp32 -> [n][640] bf16 hi/lo ----------------
__global__ __launch_bounds__(128) void wsplit_kernel(
    const float* __restrict__ W_ih, const float* __restrict__ W_hh)
{
    const int n = blockIdx.x;             // 0..2047
    const int j = n >> 2, g = n & 3;
    const int col = g * Hsz + j;
    for (int k = threadIdx.x; k < 640; k += 128) {
        float v = (k < Fsz) ? W_ih[k * G4H + col] : W_hh[(k - Fsz) * G4H + col];
        unsigned short h, l;
        bsplit(v, h, l);
        ((unsigned short*)g_wh)[n * 640 + k] = h;
        ((unsigned short*)g_wl)[n * 640 + k] = l;
    }
}

// ---------------- x split ----------------
__global__ __launch_bounds__(256) void xsplit_kernel(const float* __restrict__ x) {
    int i4 = blockIdx.x * blockDim.x + threadIdx.x;
    float4 v = *(const float4*)(x + (size_t)i4 * 4);
    unsigned short h[4], l[4];
    bsplit(v.x, h[0], l[0]); bsplit(v.y, h[1], l[1]);
    bsplit(v.z, h[2], l[2]); bsplit(v.w, h[3], l[3]);
    uint2 hp, lp;
    hp.x = (uint32_t)h[0] | ((uint32_t)h[1] << 16);
    hp.y = (uint32_t)h[2] | ((uint32_t)h[3] << 16);
    lp.x = (uint32_t)l[0] | ((uint32_t)l[1] << 16);
    lp.y = (uint32_t)l[2] | ((uint32_t)l[3] << 16);
    *(uint2*)((unsigned short*)g_xh + (size_t)i4 * 4) = hp;
    *(uint2*)((unsigned short*)g_xl + (size_t)i4 * 4) = lp;
}

// ---------------- context-gate GEMMs ----------------
__global__ __launch_bounds__(256) void ctx_gemm_kernel(
    const float* __restrict__ Aext, const float* __restrict__ W,
    const float* __restrict__ bias, int mode)
{
    const int K   = (mode == 0) ? 64 : 512;
    const int lda = (mode == 0) ? 64 : 512;
    const int ldw = (mode == 0) ? 512 : 1536;
    const int ldc = ldw;
    const float* A = (mode == 0) ? Aext : g_t1;
    float* Cout    = (mode == 0) ? g_t1 : g_ctx;

    const int n0 = blockIdx.x * 64;
    const int m0 = blockIdx.y * 64;
    const int tid = threadIdx.x;
    const int tc = tid & 15;
    const int rg = tid >> 4;

    __shared__ float As[16][68];
    __shared__ float Ws[16][68];

    float4 acc[4];
#pragma unroll
    for (int i = 0; i < 4; i++) acc[i] = make_float4(0.f, 0.f, 0.f, 0.f);

    for (int k0 = 0; k0 < K; k0 += 16) {
#pragma unroll
        for (int u = 0; u < 4; u++) {
            int i = tid + u * 256;
            int r = i >> 4, kk = i & 15;
            As[kk][r] = A[(m0 + r) * lda + k0 + kk];
            int kr = i >> 6, c = i & 63;
            Ws[kr][c] = W[(k0 + kr) * ldw + n0 + c];
        }
        __syncthreads();
#pragma unroll
        for (int kk = 0; kk < 16; kk++) {
            float4 w = *(const float4*)&Ws[kk][tc * 4];
            float4 a = *(const float4*)&As[kk][rg * 4];
            acc[0].x += a.x * w.x; acc[0].y += a.x * w.y; acc[0].z += a.x * w.z; acc[0].w += a.x * w.w;
            acc[1].x += a.y * w.x; acc[1].y += a.y * w.y; acc[1].z += a.y * w.z; acc[1].w += a.y * w.w;
            acc[2].x += a.z * w.x; acc[2].y += a.z * w.y; acc[2].z += a.z * w.z; acc[2].w += a.z * w.w;
            acc[3].x += a.w * w.x; acc[3].y += a.w * w.y; acc[3].z += a.w * w.z; acc[3].w += a.w * w.w;
        }
        __syncthreads();
    }

    int col = n0 + tc * 4;
    float4 bv = *(const float4*)&bias[col];
#pragma unroll
    for (int ri = 0; ri < 4; ri++) {
        int row = m0 + rg * 4 + ri;
        float4 v = acc[ri];
        v.x += bv.x; v.y += bv.y; v.z += bv.z; v.w += bv.w;
        if (mode == 0) {
            v.x = fmaxf(v.x, 0.f); v.y = fmaxf(v.y, 0.f);
            v.z = fmaxf(v.z, 0.f); v.w = fmaxf(v.w, 0.f);
        } else {
            v.x = sigmoidf_(v.x); v.y = sigmoidf_(v.y);
            v.z = sigmoidf_(v.z); v.w = sigmoidf_(v.w);
        }
        *(float4*)&Cout[row * ldc + col] = v;
    }
}

// ---------------- persistent LSTM: all 128 timesteps in one launch ----------------
// 128 blocks = 4 m-groups (64 batch rows) x 32 n-slices (64 interleaved cols = 16 j).
// W slice (hi+lo) resident in smem; c, ctx, biases resident in registers.
// Global software barrier between steps (all 128 blocks resident: 1 block/SM).
__global__ __launch_bounds__(256, 1) void lstm_persist(
    const float* __restrict__ b_ih, const float* __restrict__ b_hh)
{
    extern __shared__ char smbuf[];
    const uint32_t sb = smem_to_u32(smbuf);
    const int tid = threadIdx.x;
    const int lane = tid & 31, wid = tid >> 5;
    const int bx = blockIdx.x;
    const int n0 = (bx & 31) * 64, j0 = (bx & 31) * 16;
    const int m0 = (bx >> 5) * 64;

    const int m0w = (wid >> 1) * 16;
    const int n0w = (wid & 1) * 32;
    const int rA = m0w + (lane & 15);
    const uint32_t offA = rA * 32 + ((((lane >> 4) ^ (rA >> 2)) & 1) << 4);
    const int rB = n0w + ((lane >> 4) << 3) + (lane & 7);
    const uint32_t offB = rB * 32 + ((((lane >> 3) ^ (rB >> 2)) & 1) << 4);

    // cp.async fill coords: row = tid>>2, 16B segment s4 = tid&3
    const int cr = tid >> 2;
    const int s4 = tid & 3;
    const uint32_t adst = (s4 >> 1) * 2048 + cr * 32 + (((s4 ^ (cr >> 2)) & 1) << 4);

    // ---- load resident W slice (hi + lo), once ----
    {
        const size_t wrow = (size_t)(n0 + cr) * 640 + s4 * 8;
#pragma unroll 1
        for (int c = 0; c < NCH; c++) {
            cp16(sb + WHI_OFF + c * 4096 + adst, g_wh + wrow + c * 32);
            cp16(sb + WLO_OFF + c * 4096 + adst, g_wl + wrow + c * 32);
        }
        CP_COMMIT(); CP_WAIT(0);
    }
    __syncthreads();

    // ---- epilogue-persistent registers: biases, ctx, cell state ----
    const int jl = tid & 15, rg = tid >> 4;
    const int j = j0 + jl;
    const float bi  = b_ih[j]        + b_hh[j];
    const float bff = b_ih[j + 512]  + b_hh[j + 512];
    const float bg  = b_ih[j + 1024] + b_hh[j + 1024];
    const float bo  = b_ih[j + 1536] + b_hh[j + 1536];
    float creg[4], cti[4], ctf[4], cto[4];
#pragma unroll
    for (int ri = 0; ri < 4; ri++) {
        const int b = m0 + rg * 4 + ri;
        cti[ri] = g_ctx[(size_t)b * (3 * Hsz) + j];
        ctf[ri] = g_ctx[(size_t)b * (3 * Hsz) + j + 512];
        cto[ri] = g_ctx[(size_t)b * (3 * Hsz) + j + 1024];
        creg[ri] = 0.f;
    }

    float* Cs = (float*)(smbuf + ABASE);

#pragma unroll 1
    for (int t = 0; t < Ssz; t++) {
        const __nv_bfloat16* hh = g_hh[t & 1];
        const __nv_bfloat16* hl = g_hl[t & 1];

        auto fill = [&](int cc) {
            const uint32_t st = sb + ABASE + (cc % 3) * 8192;
            const int ck = cc * 32;
            size_t aoff;
            const __nv_bfloat16 *ah, *al;
            if (cc < 4) {
                ah = g_xh; al = g_xl;
                aoff = (size_t)(m0 + cr) * (Ssz * Fsz) + (size_t)t * Fsz + ck + s4 * 8;
            } else {
                ah = hh; al = hl;
                aoff = (size_t)(m0 + cr) * Hsz + (ck - Fsz) + s4 * 8;
            }
            cp16(st + adst,        ah + aoff);
            cp16(st + 4096 + adst, al + aoff);
        };

        float acc[4][4];
#pragma unroll
        for (int i = 0; i < 4; i++)
#pragma unroll
            for (int q = 0; q < 4; q++) acc[i][q] = 0.f;

        fill(0); CP_COMMIT();
        fill(1); CP_COMMIT();

#pragma unroll 1
        for (int c = 0; c < NCH; c++) {
            if (c < NCH - 1) { CP_WAIT(1); } else { CP_WAIT(0); }
            __syncthreads();
            if (c + 2 < NCH) fill(c + 2);
            CP_COMMIT();

            const uint32_t st = sb + ABASE + (c % 3) * 8192;
            const uint32_t wst = sb + c * 4096;
#pragma unroll
            for (int kb = 0; kb < 2; kb++) {
                uint32_t a0, a1, a2, a3, l0, l1, l2, l3;
                LDSM4(a0, a1, a2, a3, st + kb * 2048 + offA);
                LDSM4(l0, l1, l2, l3, st + 4096 + kb * 2048 + offA);
                uint32_t bh0, bh1, bh2, bh3, bh4, bh5, bh6, bh7;
                LDSM4(bh0, bh1, bh2, bh3, wst + WHI_OFF + kb * 2048 + offB);
                LDSM4(bh4, bh5, bh6, bh7, wst + WHI_OFF + kb * 2048 + offB + 512);
                uint32_t bl0, bl1, bl2, bl3, bl4, bl5, bl6, bl7;
                LDSM4(bl0, bl1, bl2, bl3, wst + WLO_OFF + kb * 2048 + offB);
                LDSM4(bl4, bl5, bl6, bl7, wst + WLO_OFF + kb * 2048 + offB + 512);

                MMA(acc[0], a0, a1, a2, a3, bh0, bh1);
                MMA(acc[1], a0, a1, a2, a3, bh2, bh3);
                MMA(acc[2], a0, a1, a2, a3, bh4, bh5);
                MMA(acc[3], a0, a1, a2, a3, bh6, bh7);
                MMA(acc[0], l0, l1, l2, l3, bh0, bh1);
                MMA(acc[1], l0, l1, l2, l3, bh2, bh3);
                MMA(acc[2], l0, l1, l2, l3, bh4, bh5);
                MMA(acc[3], l0, l1, l2, l3, bh6, bh7);
                MMA(acc[0], a0, a1, a2, a3, bl0, bl1);
                MMA(acc[1], a0, a1, a2, a3, bl2, bl3);
                MMA(acc[2], a0, a1, a2, a3, bl4, bl5);
                MMA(acc[3], a0, a1, a2, a3, bl6, bl7);
            }
        }

        // ---- C through smem, fused LSTM epilogue ----
        __syncthreads();
#pragma unroll
        for (int nt = 0; nt < 4; nt++) {
            const int colb = n0w + nt * 8 + (lane & 3) * 2;
            const int row = m0w + (lane >> 2);
            Cs[row * 64 + colb]           = acc[nt][0];
            Cs[row * 64 + colb + 1]       = acc[nt][1];
            Cs[(row + 8) * 64 + colb]     = acc[nt][2];
            Cs[(row + 8) * 64 + colb + 1] = acc[nt][3];
        }
        __syncthreads();

        __nv_bfloat16* hho = g_hh[(t + 1) & 1];
        __nv_bfloat16* hlo = g_hl[(t + 1) & 1];
#pragma unroll
        for (int ri = 0; ri < 4; ri++) {
            const int row = rg * 4 + ri;
            const int b = m0 + row;
            float4 gv = *(float4*)&Cs[row * 64 + jl * 4];
            float iv = sigmoidf_(gv.x + bi)  * cti[ri];
            float fv = sigmoidf_(gv.y + bff) * ctf[ri];
            float gg = tanhf(gv.z + bg);
            float ov = sigmoidf_(gv.w + bo)  * cto[ri];
            float cn = fv * creg[ri] + iv * gg;
            creg[ri] = cn;
            float hn = ov * tanhf(cn);
            const int idx = b * Hsz + j;
            __nv_bfloat16 hb = __float2bfloat16(hn);
            hho[idx] = hb;
            hlo[idx] = __float2bfloat16(hn - __bfloat162float(hb));
            if (t == Ssz - 1) g_h[0][idx] = hn;
        }

        // ---- global barrier ----
        __threadfence();
        __syncthreads();
        if (tid == 0) {
            atomicAdd(&g_bar, 1u);
            const unsigned int tgt = 128u * (unsigned)(t + 1);
            unsigned int v;
            do {
                asm volatile("ld.global.acquire.gpu.u32 %0, [%1];" : "=r"(v) : "l"(&g_bar));
                if (v >= tgt) break;
                __nanosleep(32);
            } while (true);
        }
        __syncthreads();
    }
}

// ---------------- mu / log_var / z ----------------
__global__ __launch_bounds__(512) void mulv_kernel(
    const float* __restrict__ mu_w, const float* __restrict__ mu_b,
    const float* __restrict__ lv_w, const float* __restrict__ lv_b,
    const float* __restrict__ eps, float* __restrict__ out)
{
    const int b = blockIdx.x;
    const int tid = threadIdx.x;
    __shared__ float sh[512];
    __shared__ float smu[16], slv[16];

    sh[tid] = g_h[0][b * Hsz + tid];
    __syncthreads();

    const int w = tid >> 5, lane = tid & 31;
    const int l = w;
    float sm = 0.f, sl = 0.f;
    for (int k = lane; k < Hsz; k += 32) {
        float hv = sh[k];
        sm += hv * mu_w[k * Lsz + l];
        sl += hv * lv_w[k * Lsz + l];
    }
#pragma unroll
    for (int o = 16; o > 0; o >>= 1) {
        sm += __shfl_down_sync(0xffffffffu, sm, o);
        sl += __shfl_down_sync(0xffffffffu, sl, o);
    }
    if (lane == 0) { smu[l] = sm; slv[l] = sl; }
    __syncthreads();

    if (tid < Lsz) {
        float mu = smu[tid] + mu_b[tid];
        float lv = slv[tid] + lv_b[tid];
        out[Bsz * Fsz + b * Lsz + tid] = mu;
        out[Bsz * Fsz + Bsz * Lsz + b * Lsz + tid] = lv;
        g_z[b * Lsz + tid] = mu + eps[b * Lsz + tid] * expf(0.5f * lv);
    }
}

// ---------------- decoder ----------------
__global__ __launch_bounds__(128) void dec_kernel(
    const float* __restrict__ dec_w1, const float* __restrict__ dec_b1,
    const float* __restrict__ dec_w2, const float* __restrict__ dec_b2,
    float* __restrict__ out)
{
    const int b = blockIdx.x;
    const int tid = threadIdx.x;
    __shared__ float sz[16];
    __shared__ float st[512];

    if (tid < 16) sz[tid] = g_z[b * Lsz + tid];
    __syncthreads();

#pragma unroll
    for (int u = 0; u < 4; u++) {
        int jj = tid + u * 128;
        float s = dec_b1[jj];
#pragma unroll
        for (int k = 0; k < 16; k++) s += sz[k] * dec_w1[k * Hsz + jj];
        st[jj] = fmaxf(s, 0.f);
    }
    __syncthreads();

    float r = dec_b2[tid];
    for (int k = 0; k < Hsz; k++) r += st[k] * dec_w2[k * Fsz + tid];
    out[b * Fsz + tid] = r;
}

// ---------------- launch ----------------
extern "C" void kernel_launch(void* const* d_in, const int* in_sizes, int n_in,
                              void* d_out, int out_size)
{
    const float* x       = (const float*)d_in[0];
    const float* context = (const float*)d_in[1];
    const float* eps     = (const float*)d_in[2];
    const float* W_ih    = (const float*)d_in[3];
    const float* b_ih    = (const float*)d_in[4];
    const float* W_hh    = (const float*)d_in[5];
    const float* b_hh    = (const float*)d_in[6];
    const float* cg_w1   = (const float*)d_in[7];
    const float* cg_b1   = (const float*)d_in[8];
    const float* cg_w2   = (const float*)d_in[9];
    const float* cg_b2   = (const float*)d_in[10];
    const float* mu_w    = (const float*)d_in[11];
    const float* mu_b    = (const float*)d_in[12];
    const float* lv_w    = (const float*)d_in[13];
    const float* lv_b    = (const float*)d_in[14];
    const float* dec_w1  = (const float*)d_in[15];
    const float* dec_b1  = (const float*)d_in[16];
    const float* dec_w2  = (const float*)d_in[17];
    const float* dec_b2  = (const float*)d_in[18];
    float* out = (float*)d_out;

    static int smem_set = 0;
    if (!smem_set) {
        cudaFuncSetAttribute(lstm_persist, cudaFuncAttributeMaxDynamicSharedMemorySize,
                             SMEM_PERSIST);
        smem_set = 1;
    }

    init_kernel<<<(Bsz * Hsz + 511) / 512, 512>>>();
    wsplit_kernel<<<2048, 128>>>(W_ih, W_hh);
    xsplit_kernel<<<(Bsz * Ssz * Fsz) / (256 * 4), 256>>>(x);

    ctx_gemm_kernel<<<dim3(8, 4), 256>>>(context, cg_w1, cg_b1, 0);
    ctx_gemm_kernel<<<dim3(24, 4), 256>>>(nullptr, cg_w2, cg_b2, 1);

    // entire 128-step recurrence in ONE persistent launch
    lstm_persist<<<128, 256, SMEM_PERSIST>>>(b_ih, b_hh);

    mulv_kernel<<<Bsz, 512>>>(mu_w, mu_b, lv_w, lv_b, eps, out);
    dec_kernel<<<Bsz, 128>>>(dec_w1, dec_b1, dec_w2, dec_b2, out);
}

// round 6
// speedup vs baseline: 3.0979x; 1.1503x over previous
#include <cuda_runtime.h>
#include <cuda_bf16.h>
#include <math.h>
#include <stdint.h>

#define Bsz 256
#define Ssz 128
#define Fsz 128
#define Hsz 512
#define G4H 2048
#define Csz 64
#define Lsz 16
#define NCH 20            // K=640 in k32 chunks

// persistent-kernel smem layout
#define WHI_OFF 0                 // resident W hi: 20 x 4KB
#define WLO_OFF 81920             // resident W lo: 20 x 4KB
#define ABASE   163840            // 3 A stages x 8KB (hi 4KB | lo 4KB); also C epilogue
#define MB_OFF  (ABASE + 3 * 8192)   // 4 mbarriers (3 stages + W)
#define SMEM_PERSIST (MB_OFF + 64)

// ---------------- device scratch ----------------
__device__ float g_h[Bsz * Hsz];        // final h (fp32) for mulv
__device__ float g_ctx[Bsz * 3 * Hsz];
__device__ float g_t1[Bsz * Hsz];
__device__ float g_z[Bsz * Lsz];
__device__ unsigned int g_bar;
__device__ __nv_bfloat16 g_wh[2048 * 640];
__device__ __nv_bfloat16 g_wl[2048 * 640];
__device__ __nv_bfloat16 g_xh[Bsz * Ssz * Fsz];
__device__ __nv_bfloat16 g_xl[Bsz * Ssz * Fsz];
// byte-exact smem images for bulk copies
__device__ unsigned char g_wimg[32 * 163840];              // per n-slice: [hi 20x4KB][lo 20x4KB]
__device__ unsigned char g_ximg[128 * 4 * 4 * 8192];       // [t][mgrp][chunk0-3][8KB]
__device__ unsigned char g_himg[2][4 * 16 * 8192];         // [par][mgrp][chunk4-19][8KB]

__device__ __forceinline__ float sigmoidf_(float v) { return 1.0f / (1.0f + expf(-v)); }

__device__ __forceinline__ uint32_t smem_to_u32(const void* p) {
    uint32_t a;
    asm("{ .reg .u64 t; cvta.to.shared.u64 t, %1; cvt.u32.u64 %0, t; }" : "=r"(a) : "l"(p));
    return a;
}

#define MBARRIER_INIT(addr, cnt) \
    asm volatile("mbarrier.init.shared.b64 [%0], %1;" :: "r"((uint32_t)(addr)), "r"((uint32_t)(cnt)) : "memory")
#define MBARRIER_EXPECT_TX(addr, bytes) \
    asm volatile("mbarrier.arrive.expect_tx.shared.b64 _, [%0], %1;" :: "r"((uint32_t)(addr)), "r"((uint32_t)(bytes)) : "memory")
#define MBARRIER_WAIT_PARITY(mbar_smem_addr, phase_parity) do { \
    uint32_t _mbar = (uint32_t)(mbar_smem_addr); \
    uint32_t _parity = (uint32_t)(phase_parity); \
    uint32_t _done; \
    asm volatile("{\n\t.reg .pred p;\n\t" \
        "mbarrier.try_wait.parity.acquire.cta.shared::cta.b64 p, [%1], %2;\n\t" \
        "selp.b32 %0, 1, 0, p;\n\t}" \
        : "=r"(_done) : "r"(_mbar), "r"(_parity) : "memory"); \
    if (!_done) { \
        asm volatile("{\n\t.reg .pred P1;\n\t" \
            "WAIT_LOOP_%=:\n\t" \
            "mbarrier.try_wait.parity.acquire.cta.shared::cta.b64 P1, [%0], %1, 0x989680;\n\t" \
            "@P1 bra.uni WAIT_DONE_%=;\n\t" \
            "bra.uni WAIT_LOOP_%=;\n\t" \
            "WAIT_DONE_%=:\n\t}" \
            :: "r"(_mbar), "r"(_parity) : "memory"); \
    } \
} while (0)
#define FENCE_ASYNC_SHARED() asm volatile("fence.proxy.async.shared::cta;" ::: "memory")

__device__ __forceinline__ void bulk_g2s(uint32_t dst, const void* src, uint32_t bytes, uint32_t mbar) {
    asm volatile("cp.async.bulk.shared::cluster.global.mbarrier::complete_tx::bytes [%0], [%1], %2, [%3];"
                 :: "r"(dst), "l"(src), "r"(bytes), "r"(mbar) : "memory");
}

#define LDSM4(r0, r1, r2, r3, a) \
    asm volatile("ldmatrix.sync.aligned.m8n8.x4.shared.b16 {%0,%1,%2,%3}, [%4];" \
                 : "=r"(r0), "=r"(r1), "=r"(r2), "=r"(r3) : "r"(a))

#define MMA(c, a0, a1, a2, a3, b0, b1) \
    asm volatile("mma.sync.aligned.m16n8k16.row.col.f32.bf16.bf16.f32 " \
                 "{%0,%1,%2,%3}, {%4,%5,%6,%7}, {%8,%9}, {%0,%1,%2,%3};" \
                 : "+f"((c)[0]), "+f"((c)[1]), "+f"((c)[2]), "+f"((c)[3]) \
                 : "r"(a0), "r"(a1), "r"(a2), "r"(a3), "r"(b0), "r"(b1))

__device__ __forceinline__ void bsplit(float v, unsigned short& h, unsigned short& l) {
    __nv_bfloat16 bh = __float2bfloat16(v);
    float r = v - __bfloat162float(bh);
    __nv_bfloat16 bl = __float2bfloat16(r);
    h = *(unsigned short*)&bh;
    l = *(unsigned short*)&bl;
}

// ---------------- init: zero h0 images + barrier counter ----------------
__global__ void init_kernel() {
    int i = blockIdx.x * blockDim.x + threadIdx.x;
    if (i == 0) g_bar = 0u;
    if (i < (4 * 16 * 8192) / 8) ((unsigned long long*)g_himg[0])[i] = 0ull;
}

// ---------------- W split: [k][2048] fp32 -> [n][640] bf16 hi/lo ----------------
__global__ __launch_bounds__(128) void wsplit_kernel(
    const float* __restrict__ W_ih, const float* __restrict__ W_hh)
{
    const int n = blockIdx.x;
    const int j = n >> 2, g = n & 3;
    const int col = g * Hsz + j;
    for (int k = threadIdx.x; k < 640; k += 128) {
        float v = (k < Fsz) ? W_ih[k * G4H + col] : W_hh[(k - Fsz) * G4H + col];
        unsigned short h, l;
        bsplit(v, h, l);
        ((unsigned short*)g_wh)[n * 640 + k] = h;
        ((unsigned short*)g_wl)[n * 640 + k] = l;
    }
}

// ---------------- W image pack (byte-exact smem tile, swizzle baked in) ----------------
__global__ __launch_bounds__(256) void wimg_kernel() {
    const int ns = blockIdx.x;                    // 0..31
    const int cr = threadIdx.x >> 2, s4 = threadIdx.x & 3;
    const int n = ns * 64 + cr;
    const uint32_t seg = (s4 >> 1) * 2048 + cr * 32 + (((s4) ^ (cr >> 2)) & 1) * 16;
    unsigned char* base = g_wimg + (size_t)ns * 163840;
#pragma unroll 1
    for (int c = 0; c < NCH; c++) {
        const size_t srco = (size_t)n * 640 + c * 32 + s4 * 8;
        *(uint4*)(base + c * 4096 + seg)         = *(const uint4*)(g_wh + srco);
        *(uint4*)(base + 81920 + c * 4096 + seg) = *(const uint4*)(g_wl + srco);
    }
}

// ---------------- x split ----------------
__global__ __launch_bounds__(256) void xsplit_kernel(const float* __restrict__ x) {
    int i4 = blockIdx.x * blockDim.x + threadIdx.x;
    float4 v = *(const float4*)(x + (size_t)i4 * 4);
    unsigned short h[4], l[4];
    bsplit(v.x, h[0], l[0]); bsplit(v.y, h[1], l[1]);
    bsplit(v.z, h[2], l[2]); bsplit(v.w, h[3], l[3]);
    uint2 hp, lp;
    hp.x = (uint32_t)h[0] | ((uint32_t)h[1] << 16);
    hp.y = (uint32_t)h[2] | ((uint32_t)h[3] << 16);
    lp.x = (uint32_t)l[0] | ((uint32_t)l[1] << 16);
    lp.y = (uint32_t)l[2] | ((uint32_t)l[3] << 16);
    *(uint2*)((unsigned short*)g_xh + (size_t)i4 * 4) = hp;
    *(uint2*)((unsigned short*)g_xl + (size_t)i4 * 4) = lp;
}

// ---------------- x image pack ----------------
__global__ __launch_bounds__(256) void ximg_kernel() {
    const int bid = blockIdx.x;                   // 0..511
    const int t = bid >> 2, mg = bid & 3;
    const int cr = threadIdx.x >> 2, s4 = threadIdx.x & 3;
    const int b = mg * 64 + cr;
    const uint32_t seg = (s4 >> 1) * 2048 + cr * 32 + (((s4) ^ (cr >> 2)) & 1) * 16;
    unsigned char* base = g_ximg + (size_t)(t * 4 + mg) * 4 * 8192;
#pragma unroll
    for (int c = 0; c < 4; c++) {
        const size_t srco = (size_t)b * (Ssz * Fsz) + (size_t)t * Fsz + c * 32 + s4 * 8;
        *(uint4*)(base + c * 8192 + seg)        = *(const uint4*)(g_xh + srco);
        *(uint4*)(base + c * 8192 + 4096 + seg) = *(const uint4*)(g_xl + srco);
    }
}

// ---------------- context-gate GEMMs ----------------
__global__ __launch_bounds__(256) void ctx_gemm_kernel(
    const float* __restrict__ Aext, const float* __restrict__ W,
    const float* __restrict__ bias, int mode)
{
    const int K   = (mode == 0) ? 64 : 512;
    const int lda = (mode == 0) ? 64 : 512;
    const int ldw = (mode == 0) ? 512 : 1536;
    const int ldc = ldw;
    const float* A = (mode == 0) ? Aext : g_t1;
    float* Cout    = (mode == 0) ? g_t1 : g_ctx;

    const int n0 = blockIdx.x * 64;
    const int m0 = blockIdx.y * 64;
    const int tid = threadIdx.x;
    const int tc = tid & 15;
    const int rg = tid >> 4;

    __shared__ float As[16][68];
    __shared__ float Ws[16][68];

    float4 acc[4];
#pragma unroll
    for (int i = 0; i < 4; i++) acc[i] = make_float4(0.f, 0.f, 0.f, 0.f);

    for (int k0 = 0; k0 < K; k0 += 16) {
#pragma unroll
        for (int u = 0; u < 4; u++) {
            int i = tid + u * 256;
            int r = i >> 4, kk = i & 15;
            As[kk][r] = A[(m0 + r) * lda + k0 + kk];
            int kr = i >> 6, c = i & 63;
            Ws[kr][c] = W[(k0 + kr) * ldw + n0 + c];
        }
        __syncthreads();
#pragma unroll
        for (int kk = 0; kk < 16; kk++) {
            float4 w = *(const float4*)&Ws[kk][tc * 4];
            float4 a = *(const float4*)&As[kk][rg * 4];
            acc[0].x += a.x * w.x; acc[0].y += a.x * w.y; acc[0].z += a.x * w.z; acc[0].w += a.x * w.w;
            acc[1].x += a.y * w.x; acc[1].y += a.y * w.y; acc[1].z += a.y * w.z; acc[1].w += a.y * w.w;
            acc[2].x += a.z * w.x; acc[2].y += a.z * w.y; acc[2].z += a.z * w.z; acc[2].w += a.z * w.w;
            acc[3].x += a.w * w.x; acc[3].y += a.w * w.y; acc[3].z += a.w * w.z; acc[3].w += a.w * w.w;
        }
        __syncthreads();
    }

    int col = n0 + tc * 4;
    float4 bv = *(const float4*)&bias[col];
#pragma unroll
    for (int ri = 0; ri < 4; ri++) {
        int row = m0 + rg * 4 + ri;
        float4 v = acc[ri];
        v.x += bv.x; v.y += bv.y; v.z += bv.z; v.w += bv.w;
        if (mode == 0) {
            v.x = fmaxf(v.x, 0.f); v.y = fmaxf(v.y, 0.f);
            v.z = fmaxf(v.z, 0.f); v.w = fmaxf(v.w, 0.f);
        } else {
            v.x = sigmoidf_(v.x); v.y = sigmoidf_(v.y);
            v.z = sigmoidf_(v.z); v.w = sigmoidf_(v.w);
        }
        *(float4*)&Cout[row * ldc + col] = v;
    }
}

// ---------------- persistent LSTM: bulk-copy pipeline ----------------
__global__ __launch_bounds__(256, 1) void lstm_persist(
    const float* __restrict__ b_ih, const float* __restrict__ b_hh)
{
    extern __shared__ char smbuf[];
    const uint32_t sb = smem_to_u32(smbuf);
    const int tid = threadIdx.x;
    const int lane = tid & 31, wid = tid >> 5;
    const int bx = blockIdx.x;
    const int nsl = bx & 31;
    const int n0 = nsl * 64, j0 = nsl * 16;
    const int mg = bx >> 5;
    const int m0 = mg * 64;

    const int m0w = (wid >> 1) * 16;
    const int n0w = (wid & 1) * 32;
    const int rA = m0w + (lane & 15);
    const uint32_t offA = rA * 32 + ((((lane >> 4) ^ (rA >> 2)) & 1) << 4);
    const int rB = n0w + ((lane >> 4) << 3) + (lane & 7);
    const uint32_t offB = rB * 32 + ((((lane >> 3) ^ (rB >> 2)) & 1) << 4);

    const uint32_t mb0 = sb + MB_OFF;        // stage barriers at +0,+8,+16; W at +24
    if (tid == 0) {
        MBARRIER_INIT(mb0 + 0, 1);
        MBARRIER_INIT(mb0 + 8, 1);
        MBARRIER_INIT(mb0 + 16, 1);
        MBARRIER_INIT(mb0 + 24, 1);
    }
    FENCE_ASYNC_SHARED();
    __syncthreads();

    // ---- resident W slice: one-shot bulk load ----
    if (tid == 0) {
        MBARRIER_EXPECT_TX(mb0 + 24, 163840u);
        const unsigned char* src = g_wimg + (size_t)nsl * 163840;
#pragma unroll
        for (int i = 0; i < 10; i++)
            bulk_g2s(sb + i * 16384, src + i * 16384, 16384u, mb0 + 24);
    }
    MBARRIER_WAIT_PARITY(mb0 + 24, 0);
    __syncthreads();

    // ---- epilogue-persistent registers ----
    const int jl = tid & 15, rg = tid >> 4;
    const int j = j0 + jl;
    const float bi  = b_ih[j]        + b_hh[j];
    const float bff = b_ih[j + 512]  + b_hh[j + 512];
    const float bg  = b_ih[j + 1024] + b_hh[j + 1024];
    const float bo  = b_ih[j + 1536] + b_hh[j + 1536];
    float creg[4], cti[4], ctf[4], cto[4];
#pragma unroll
    for (int ri = 0; ri < 4; ri++) {
        const int b = m0 + rg * 4 + ri;
        cti[ri] = g_ctx[(size_t)b * (3 * Hsz) + j];
        ctf[ri] = g_ctx[(size_t)b * (3 * Hsz) + j + 512];
        cto[ri] = g_ctx[(size_t)b * (3 * Hsz) + j + 1024];
        creg[ri] = 0.f;
    }
    // h image write coords (j fixed per thread)
    const int hc = j >> 5, kj = j & 31, s4h = kj >> 3, eh = kj & 7;
    const uint32_t hoffbase = (uint32_t)(mg * 16 + hc) * 8192 +
                              (s4h >> 1) * 2048 + (eh << 1);
    float* Cs = (float*)(smbuf + ABASE);

    unsigned phbits = 0;

#pragma unroll 1
    for (int t = 0; t < Ssz; t++) {
        const int par = t & 1;
        bool bar_ok = (t == 0);

        // producer fill: one 8KB bulk copy per chunk
        auto fill = [&](int cc) {
            if (cc >= 4 && !bar_ok) {
                const unsigned tgt = 128u * (unsigned)t;
                unsigned v;
                do {
                    asm volatile("ld.global.acquire.gpu.u32 %0, [%1];" : "=r"(v) : "l"(&g_bar));
                    if (v >= tgt) break;
                    __nanosleep(32);
                } while (true);
                bar_ok = true;
            }
            const int s2 = cc % 3;
            const unsigned char* src = (cc < 4)
                ? g_ximg + ((size_t)(t * 4 + mg) * 4 + cc) * 8192
                : g_himg[par] + (size_t)(mg * 16 + (cc - 4)) * 8192;
            MBARRIER_EXPECT_TX(mb0 + s2 * 8, 8192u);
            bulk_g2s(sb + ABASE + s2 * 8192, src, 8192u, mb0 + s2 * 8);
        };

        if (tid == 0) { FENCE_ASYNC_SHARED(); fill(0); fill(1); }

        float acc[4][4];
#pragma unroll
        for (int i = 0; i < 4; i++)
#pragma unroll
            for (int q = 0; q < 4; q++) acc[i][q] = 0.f;

#pragma unroll 1
        for (int c = 0; c < NCH; c++) {
            const int s2 = c % 3;
            MBARRIER_WAIT_PARITY(mb0 + s2 * 8, (phbits >> s2) & 1u);
            phbits ^= (1u << s2);
            __syncthreads();
            if (c + 2 < NCH && tid == 0) fill(c + 2);

            const uint32_t st = sb + ABASE + s2 * 8192;
            const uint32_t wst = sb + c * 4096;
#pragma unroll
            for (int kb = 0; kb < 2; kb++) {
                uint32_t a0, a1, a2, a3, l0, l1, l2, l3;
                LDSM4(a0, a1, a2, a3, st + kb * 2048 + offA);
                LDSM4(l0, l1, l2, l3, st + 4096 + kb * 2048 + offA);
                uint32_t bh0, bh1, bh2, bh3, bh4, bh5, bh6, bh7;
                LDSM4(bh0, bh1, bh2, bh3, wst + WHI_OFF + kb * 2048 + offB);
                LDSM4(bh4, bh5, bh6, bh7, wst + WHI_OFF + kb * 2048 + offB + 512);
                uint32_t bl0, bl1, bl2, bl3, bl4, bl5, bl6, bl7;
                LDSM4(bl0, bl1, bl2, bl3, wst + WLO_OFF + kb * 2048 + offB);
                LDSM4(bl4, bl5, bl6, bl7, wst + WLO_OFF + kb * 2048 + offB + 512);

                MMA(acc[0], a0, a1, a2, a3, bh0, bh1);
                MMA(acc[1], a0, a1, a2, a3, bh2, bh3);
                MMA(acc[2], a0, a1, a2, a3, bh4, bh5);
                MMA(acc[3], a0, a1, a2, a3, bh6, bh7);
                MMA(acc[0], l0, l1, l2, l3, bh0, bh1);
                MMA(acc[1], l0, l1, l2, l3, bh2, bh3);
                MMA(acc[2], l0, l1, l2, l3, bh4, bh5);
                MMA(acc[3], l0, l1, l2, l3, bh6, bh7);
                MMA(acc[0], a0, a1, a2, a3, bl0, bl1);
                MMA(acc[1], a0, a1, a2, a3, bl2, bl3);
                MMA(acc[2], a0, a1, a2, a3, bl4, bl5);
                MMA(acc[3], a0, a1, a2, a3, bl6, bl7);
            }
        }

        // ---- C through smem (reuses stages 0+1), fused LSTM epilogue ----
        __syncthreads();
#pragma unroll
        for (int nt = 0; nt < 4; nt++) {
            const int colb = n0w + nt * 8 + (lane & 3) * 2;
            const int row = m0w + (lane >> 2);
            Cs[row * 64 + colb]           = acc[nt][0];
            Cs[row * 64 + colb + 1]       = acc[nt][1];
            Cs[(row + 8) * 64 + colb]     = acc[nt][2];
            Cs[(row + 8) * 64 + colb + 1] = acc[nt][3];
        }
        __syncthreads();

        unsigned char* himg = g_himg[(t + 1) & 1];
#pragma unroll
        for (int ri = 0; ri < 4; ri++) {
            const int row = rg * 4 + ri;
            float4 gv = *(float4*)&Cs[row * 64 + jl * 4];
            float iv = sigmoidf_(gv.x + bi)  * cti[ri];
            float fv = sigmoidf_(gv.y + bff) * ctf[ri];
            float gg = tanhf(gv.z + bg);
            float ov = sigmoidf_(gv.w + bo)  * cto[ri];
            float cn = fv * creg[ri] + iv * gg;
            creg[ri] = cn;
            float hn = ov * tanhf(cn);
            const uint32_t hoff = hoffbase + ((uint32_t)row * 32) +
                                  ((((unsigned)s4h ^ ((unsigned)row >> 2)) & 1u) << 4);
            __nv_bfloat16 hb = __float2bfloat16(hn);
            *(__nv_bfloat16*)(himg + hoff)        = hb;
            *(__nv_bfloat16*)(himg + hoff + 4096) = __float2bfloat16(hn - __bfloat162float(hb));
            if (t == Ssz - 1) g_h[(m0 + row) * Hsz + j] = hn;
        }

        __threadfence();
        __syncthreads();
        if (tid == 0) atomicAdd(&g_bar, 1u);
    }
}

// ---------------- mu / log_var / z ----------------
__global__ __launch_bounds__(512) void mulv_kernel(
    const float* __restrict__ mu_w, const float* __restrict__ mu_b,
    const float* __restrict__ lv_w, const float* __restrict__ lv_b,
    const float* __restrict__ eps, float* __restrict__ out)
{
    const int b = blockIdx.x;
    const int tid = threadIdx.x;
    __shared__ float sh[512];
    __shared__ float smu[16], slv[16];

    sh[tid] = g_h[b * Hsz + tid];
    __syncthreads();

    const int w = tid >> 5, lane = tid & 31;
    const int l = w;
    float sm = 0.f, sl = 0.f;
    for (int k = lane; k < Hsz; k += 32) {
        float hv = sh[k];
        sm += hv * mu_w[k * Lsz + l];
        sl += hv * lv_w[k * Lsz + l];
    }
#pragma unroll
    for (int o = 16; o > 0; o >>= 1) {
        sm += __shfl_down_sync(0xffffffffu, sm, o);
        sl += __shfl_down_sync(0xffffffffu, sl, o);
    }
    if (lane == 0) { smu[l] = sm; slv[l] = sl; }
    __syncthreads();

    if (tid < Lsz) {
        float mu = smu[tid] + mu_b[tid];
        float lv = slv[tid] + lv_b[tid];
        out[Bsz * Fsz + b * Lsz + tid] = mu;
        out[Bsz * Fsz + Bsz * Lsz + b * Lsz + tid] = lv;
        g_z[b * Lsz + tid] = mu + eps[b * Lsz + tid] * expf(0.5f * lv);
    }
}

// ---------------- decoder ----------------
__global__ __launch_bounds__(128) void dec_kernel(
    const float* __restrict__ dec_w1, const float* __restrict__ dec_b1,
    const float* __restrict__ dec_w2, const float* __restrict__ dec_b2,
    float* __restrict__ out)
{
    const int b = blockIdx.x;
    const int tid = threadIdx.x;
    __shared__ float sz[16];
    __shared__ float st[512];

    if (tid < 16) sz[tid] = g_z[b * Lsz + tid];
    __syncthreads();

#pragma unroll
    for (int u = 0; u < 4; u++) {
        int jj = tid + u * 128;
        float s = dec_b1[jj];
#pragma unroll
        for (int k = 0; k < 16; k++) s += sz[k] * dec_w1[k * Hsz + jj];
        st[jj] = fmaxf(s, 0.f);
    }
    __syncthreads();

    float r = dec_b2[tid];
    for (int k = 0; k < Hsz; k++) r += st[k] * dec_w2[k * Fsz + tid];
    out[b * Fsz + tid] = r;
}

// ---------------- launch ----------------
extern "C" void kernel_launch(void* const* d_in, const int* in_sizes, int n_in,
                              void* d_out, int out_size)
{
    const float* x       = (const float*)d_in[0];
    const float* context = (const float*)d_in[1];
    const float* eps     = (const float*)d_in[2];
    const float* W_ih    = (const float*)d_in[3];
    const float* b_ih    = (const float*)d_in[4];
    const float* W_hh    = (const float*)d_in[5];
    const float* b_hh    = (const float*)d_in[6];
    const float* cg_w1   = (const float*)d_in[7];
    const float* cg_b1   = (const float*)d_in[8];
    const float* cg_w2   = (const float*)d_in[9];
    const float* cg_b2   = (const float*)d_in[10];
    const float* mu_w    = (const float*)d_in[11];
    const float* mu_b    = (const float*)d_in[12];
    const float* lv_w    = (const float*)d_in[13];
    const float* lv_b    = (const float*)d_in[14];
    const float* dec_w1  = (const float*)d_in[15];
    const float* dec_b1  = (const float*)d_in[16];
    const float* dec_w2  = (const float*)d_in[17];
    const float* dec_b2  = (const float*)d_in[18];
    float* out = (float*)d_out;

    static int smem_set = 0;
    if (!smem_set) {
        cudaFuncSetAttribute(lstm_persist, cudaFuncAttributeMaxDynamicSharedMemorySize,
                             SMEM_PERSIST);
        smem_set = 1;
    }

    init_kernel<<<(4 * 16 * 8192 / 8 + 511) / 512, 512>>>();
    wsplit_kernel<<<2048, 128>>>(W_ih, W_hh);
    wimg_kernel<<<32, 256>>>();
    xsplit_kernel<<<(Bsz * Ssz * Fsz) / (256 * 4), 256>>>(x);
    ximg_kernel<<<512, 256>>>();

    ctx_gemm_kernel<<<dim3(8, 4), 256>>>(context, cg_w1, cg_b1, 0);
    ctx_gemm_kernel<<<dim3(24, 4), 256>>>(nullptr, cg_w2, cg_b2, 1);

    // entire 128-step recurrence in ONE persistent launch (bulk-copy pipeline)
    lstm_persist<<<128, 256, SMEM_PERSIST>>>(b_ih, b_hh);

    mulv_kernel<<<Bsz, 512>>>(mu_w, mu_b, lv_w, lv_b, eps, out);
    dec_kernel<<<Bsz, 128>>>(dec_w1, dec_b1, dec_w2, dec_b2, out);
}

// round 7
// speedup vs baseline: 4.0085x; 1.2939x over previous
#include <cuda_runtime.h>
#include <cuda_bf16.h>
#include <math.h>
#include <stdint.h>

#define Bsz 256
#define Ssz 128
#define Fsz 128
#define Hsz 512
#define G4H 2048
#define Csz 64
#define Lsz 16
#define CPS 10            // chunks per step (K=640 in k64 chunks)

// persistent-kernel smem layout
#define WHI_OFF 0                 // resident W hi: 20 x 4KB (k32 granularity)
#define WLO_OFF 81920             // resident W lo: 20 x 4KB
#define ABASE   163840            // 3 A stages x 16KB (two 8KB sub-tiles, each hi4K|lo4K)
#define MB_OFF  (ABASE + 3 * 16384)
#define SMEM_PERSIST (MB_OFF + 64)   // 213056

// ---------------- device scratch ----------------
__device__ float g_h[Bsz * Hsz];        // final h (fp32) for mulv
__device__ float g_ctx[Bsz * 3 * Hsz];
__device__ float g_t1[Bsz * Hsz];
__device__ float g_z[Bsz * Lsz];
__device__ unsigned int g_barm[4];      // per-m-group step counters (warp arrivals)
__device__ __nv_bfloat16 g_wh[2048 * 640];
__device__ __nv_bfloat16 g_wl[2048 * 640];
__device__ __nv_bfloat16 g_xh[Bsz * Ssz * Fsz];
__device__ __nv_bfloat16 g_xl[Bsz * Ssz * Fsz];
// byte-exact smem images for bulk copies
__device__ unsigned char g_wimg[32 * 163840];              // per n-slice: [hi 20x4KB][lo 20x4KB]
__device__ unsigned char g_ximg[128 * 4 * 4 * 8192];       // [t][mgrp][k32-chunk 0-3][8KB]
__device__ unsigned char g_himg[2][4 * 16 * 8192];         // [par][mgrp][k32-chunk 4-19][8KB]

__device__ __forceinline__ float sigmoidf_(float v) {
    return __fdividef(1.0f, 1.0f + __expf(-v));
}
__device__ __forceinline__ float tanhf_(float v) {
    float vc = fminf(fmaxf(v, -15.0f), 15.0f);
    float e = __expf(2.0f * vc);
    return __fdividef(e - 1.0f, e + 1.0f);
}

__device__ __forceinline__ uint32_t smem_to_u32(const void* p) {
    uint32_t a;
    asm("{ .reg .u64 t; cvta.to.shared.u64 t, %1; cvt.u32.u64 %0, t; }" : "=r"(a) : "l"(p));
    return a;
}

#define MBARRIER_INIT(addr, cnt) \
    asm volatile("mbarrier.init.shared.b64 [%0], %1;" :: "r"((uint32_t)(addr)), "r"((uint32_t)(cnt)) : "memory")
#define MBARRIER_EXPECT_TX(addr, bytes) \
    asm volatile("mbarrier.arrive.expect_tx.shared.b64 _, [%0], %1;" :: "r"((uint32_t)(addr)), "r"((uint32_t)(bytes)) : "memory")
#define MBARRIER_WAIT_PARITY(mbar_smem_addr, phase_parity) do { \
    uint32_t _mbar = (uint32_t)(mbar_smem_addr); \
    uint32_t _parity = (uint32_t)(phase_parity); \
    uint32_t _done; \
    asm volatile("{\n\t.reg .pred p;\n\t" \
        "mbarrier.try_wait.parity.acquire.cta.shared::cta.b64 p, [%1], %2;\n\t" \
        "selp.b32 %0, 1, 0, p;\n\t}" \
        : "=r"(_done) : "r"(_mbar), "r"(_parity) : "memory"); \
    if (!_done) { \
        asm volatile("{\n\t.reg .pred P1;\n\t" \
            "WAIT_LOOP_%=:\n\t" \
            "mbarrier.try_wait.parity.acquire.cta.shared::cta.b64 P1, [%0], %1, 0x989680;\n\t" \
            "@P1 bra.uni WAIT_DONE_%=;\n\t" \
            "bra.uni WAIT_LOOP_%=;\n\t" \
            "WAIT_DONE_%=:\n\t}" \
            :: "r"(_mbar), "r"(_parity) : "memory"); \
    } \
} while (0)
#define FENCE_ASYNC_SHARED() asm volatile("fence.proxy.async.shared::cta;" ::: "memory")

__device__ __forceinline__ void bulk_g2s(uint32_t dst, const void* src, uint32_t bytes, uint32_t mbar) {
    asm volatile("cp.async.bulk.shared::cluster.global.mbarrier::complete_tx::bytes [%0], [%1], %2, [%3];"
                 :: "r"(dst), "l"(src), "r"(bytes), "r"(mbar) : "memory");
}

#define LDSM4(r0, r1, r2, r3, a) \
    asm volatile("ldmatrix.sync.aligned.m8n8.x4.shared.b16 {%0,%1,%2,%3}, [%4];" \
                 : "=r"(r0), "=r"(r1), "=r"(r2), "=r"(r3) : "r"(a))

#define MMA(c, a0, a1, a2, a3, b0, b1) \
    asm volatile("mma.sync.aligned.m16n8k16.row.col.f32.bf16.bf16.f32 " \
                 "{%0,%1,%2,%3}, {%4,%5,%6,%7}, {%8,%9}, {%0,%1,%2,%3};" \
                 : "+f"((c)[0]), "+f"((c)[1]), "+f"((c)[2]), "+f"((c)[3]) \
                 : "r"(a0), "r"(a1), "r"(a2), "r"(a3), "r"(b0), "r"(b1))

__device__ __forceinline__ void bsplit(float v, unsigned short& h, unsigned short& l) {
    __nv_bfloat16 bh = __float2bfloat16(v);
    float r = v - __bfloat162float(bh);
    __nv_bfloat16 bl = __float2bfloat16(r);
    h = *(unsigned short*)&bh;
    l = *(unsigned short*)&bl;
}

// ---------------- init: zero h0 images + barrier counters ----------------
__global__ void init_kernel() {
    int i = blockIdx.x * blockDim.x + threadIdx.x;
    if (i < 4) g_barm[i] = 0u;
    if (i < (4 * 16 * 8192) / 8) ((unsigned long long*)g_himg[0])[i] = 0ull;
}

// ---------------- W split: [k][2048] fp32 -> [n][640] bf16 hi/lo ----------------
__global__ __launch_bounds__(128) void wsplit_kernel(
    const float* __restrict__ W_ih, const float* __restrict__ W_hh)
{
    const int n = blockIdx.x;
    const int j = n >> 2, g = n & 3;
    const int col = g * Hsz + j;
    for (int k = threadIdx.x; k < 640; k += 128) {
        float v = (k < Fsz) ? W_ih[k * G4H + col] : W_hh[(k - Fsz) * G4H + col];
        unsigned short h, l;
        bsplit(v, h, l);
        ((unsigned short*)g_wh)[n * 640 + k] = h;
        ((unsigned short*)g_wl)[n * 640 + k] = l;
    }
}

// ---------------- W image pack (byte-exact smem tile, swizzle baked in) ----------------
__global__ __launch_bounds__(256) void wimg_kernel() {
    const int ns = blockIdx.x;
    const int cr = threadIdx.x >> 2, s4 = threadIdx.x & 3;
    const int n = ns * 64 + cr;
    const uint32_t seg = (s4 >> 1) * 2048 + cr * 32 + (((s4) ^ (cr >> 2)) & 1) * 16;
    unsigned char* base = g_wimg + (size_t)ns * 163840;
#pragma unroll 1
    for (int c = 0; c < 20; c++) {
        const size_t srco = (size_t)n * 640 + c * 32 + s4 * 8;
        *(uint4*)(base + c * 4096 + seg)         = *(const uint4*)(g_wh + srco);
        *(uint4*)(base + 81920 + c * 4096 + seg) = *(const uint4*)(g_wl + srco);
    }
}

// ---------------- x split ----------------
__global__ __launch_bounds__(256) void xsplit_kernel(const float* __restrict__ x) {
    int i4 = blockIdx.x * blockDim.x + threadIdx.x;
    float4 v = *(const float4*)(x + (size_t)i4 * 4);
    unsigned short h[4], l[4];
    bsplit(v.x, h[0], l[0]); bsplit(v.y, h[1], l[1]);
    bsplit(v.z, h[2], l[2]); bsplit(v.w, h[3], l[3]);
    uint2 hp, lp;
    hp.x = (uint32_t)h[0] | ((uint32_t)h[1] << 16);
    hp.y = (uint32_t)h[2] | ((uint32_t)h[3] << 16);
    lp.x = (uint32_t)l[0] | ((uint32_t)l[1] << 16);
    lp.y = (uint32_t)l[2] | ((uint32_t)l[3] << 16);
    *(uint2*)((unsigned short*)g_xh + (size_t)i4 * 4) = hp;
    *(uint2*)((unsigned short*)g_xl + (size_t)i4 * 4) = lp;
}

// ---------------- x image pack ----------------
__global__ __launch_bounds__(256) void ximg_kernel() {
    const int bid = blockIdx.x;
    const int t = bid >> 2, mg = bid & 3;
    const int cr = threadIdx.x >> 2, s4 = threadIdx.x & 3;
    const int b = mg * 64 + cr;
    const uint32_t seg = (s4 >> 1) * 2048 + cr * 32 + (((s4) ^ (cr >> 2)) & 1) * 16;
    unsigned char* base = g_ximg + (size_t)(t * 4 + mg) * 4 * 8192;
#pragma unroll
    for (int c = 0; c < 4; c++) {
        const size_t srco = (size_t)b * (Ssz * Fsz) + (size_t)t * Fsz + c * 32 + s4 * 8;
        *(uint4*)(base + c * 8192 + seg)        = *(const uint4*)(g_xh + srco);
        *(uint4*)(base + c * 8192 + 4096 + seg) = *(const uint4*)(g_xl + srco);
    }
}

// ---------------- context-gate GEMMs ----------------
__global__ __launch_bounds__(256) void ctx_gemm_kernel(
    const float* __restrict__ Aext, const float* __restrict__ W,
    const float* __restrict__ bias, int mode)
{
    const int K   = (mode == 0) ? 64 : 512;
    const int lda = (mode == 0) ? 64 : 512;
    const int ldw = (mode == 0) ? 512 : 1536;
    const int ldc = ldw;
    const float* A = (mode == 0) ? Aext : g_t1;
    float* Cout    = (mode == 0) ? g_t1 : g_ctx;

    const int n0 = blockIdx.x * 64;
    const int m0 = blockIdx.y * 64;
    const int tid = threadIdx.x;
    const int tc = tid & 15;
    const int rg = tid >> 4;

    __shared__ float As[16][68];
    __shared__ float Ws[16][68];

    float4 acc[4];
#pragma unroll
    for (int i = 0; i < 4; i++) acc[i] = make_float4(0.f, 0.f, 0.f, 0.f);

    for (int k0 = 0; k0 < K; k0 += 16) {
#pragma unroll
        for (int u = 0; u < 4; u++) {
            int i = tid + u * 256;
            int r = i >> 4, kk = i & 15;
            As[kk][r] = A[(m0 + r) * lda + k0 + kk];
            int kr = i >> 6, c = i & 63;
            Ws[kr][c] = W[(k0 + kr) * ldw + n0 + c];
        }
        __syncthreads();
#pragma unroll
        for (int kk = 0; kk < 16; kk++) {
            float4 w = *(const float4*)&Ws[kk][tc * 4];
            float4 a = *(const float4*)&As[kk][rg * 4];
            acc[0].x += a.x * w.x; acc[0].y += a.x * w.y; acc[0].z += a.x * w.z; acc[0].w += a.x * w.w;
            acc[1].x += a.y * w.x; acc[1].y += a.y * w.y; acc[1].z += a.y * w.z; acc[1].w += a.y * w.w;
            acc[2].x += a.z * w.x; acc[2].y += a.z * w.y; acc[2].z += a.z * w.z; acc[2].w += a.z * w.w;
            acc[3].x += a.w * w.x; acc[3].y += a.w * w.y; acc[3].z += a.w * w.z; acc[3].w += a.w * w.w;
        }
        __syncthreads();
    }

    int col = n0 + tc * 4;
    float4 bv = *(const float4*)&bias[col];
#pragma unroll
    for (int ri = 0; ri < 4; ri++) {
        int row = m0 + rg * 4 + ri;
        float4 v = acc[ri];
        v.x += bv.x; v.y += bv.y; v.z += bv.z; v.w += bv.w;
        if (mode == 0) {
            v.x = fmaxf(v.x, 0.f); v.y = fmaxf(v.y, 0.f);
            v.z = fmaxf(v.z, 0.f); v.w = fmaxf(v.w, 0.f);
        } else {
            v.x = sigmoidf_(v.x); v.y = sigmoidf_(v.y);
            v.z = sigmoidf_(v.z); v.w = sigmoidf_(v.w);
        }
        *(float4*)&Cout[row * ldc + col] = v;
    }
}

// ---------------- persistent LSTM: k64 chunks, shuffle epilogue ----------------
__global__ __launch_bounds__(256, 1) void lstm_persist(
    const float* __restrict__ b_ih, const float* __restrict__ b_hh)
{
    extern __shared__ char smbuf[];
    const uint32_t sb = smem_to_u32(smbuf);
    const int tid = threadIdx.x;
    const int lane = tid & 31, wid = tid >> 5;
    const int bx = blockIdx.x;
    const int nsl = bx & 31;
    const int n0 = nsl * 64, j0 = nsl * 16;
    const int mg = bx >> 5;
    const int m0 = mg * 64;

    const int m0w = (wid >> 1) * 16;
    const int n0w = (wid & 1) * 32;
    const int rA = m0w + (lane & 15);
    const uint32_t offA = rA * 32 + ((((lane >> 4) ^ (rA >> 2)) & 1) << 4);
    const int rB = n0w + ((lane >> 4) << 3) + (lane & 7);
    const uint32_t offB = rB * 32 + ((((lane >> 3) ^ (rB >> 2)) & 1) << 4);

    const uint32_t mb0 = sb + MB_OFF;        // stage barriers +0,+8,+16; W at +24
    if (tid == 0) {
        MBARRIER_INIT(mb0 + 0, 1);
        MBARRIER_INIT(mb0 + 8, 1);
        MBARRIER_INIT(mb0 + 16, 1);
        MBARRIER_INIT(mb0 + 24, 1);
    }
    FENCE_ASYNC_SHARED();
    __syncthreads();

    // ---- resident W slice: one-shot bulk load ----
    if (tid == 0) {
        MBARRIER_EXPECT_TX(mb0 + 24, 163840u);
        const unsigned char* src = g_wimg + (size_t)nsl * 163840;
#pragma unroll
        for (int i = 0; i < 10; i++)
            bulk_g2s(sb + i * 16384, src + i * 16384, 16384u, mb0 + 24);
    }
    MBARRIER_WAIT_PARITY(mb0 + 24, 0);
    __syncthreads();

    // ---- per-cell persistent registers (fragment layout) ----
    // cell(nt): row = m0w + (lane>>2) + (lane&1)*8 ; j = j0 + (n0w>>2) + nt*2 + ((lane>>1)&1)
    const int rowc = m0w + (lane >> 2) + (lane & 1) * 8;
    const int bglob = m0 + rowc;
    int jc[4];
    float bi[4], bf4[4], bg4[4], bo4[4];
    float creg[4], cti[4], ctf[4], cto[4];
    uint32_t hoff[4];
#pragma unroll
    for (int nt = 0; nt < 4; nt++) {
        const int j = j0 + (n0w >> 2) + nt * 2 + ((lane >> 1) & 1);
        jc[nt] = j;
        bi[nt]  = b_ih[j]        + b_hh[j];
        bf4[nt] = b_ih[j + 512]  + b_hh[j + 512];
        bg4[nt] = b_ih[j + 1024] + b_hh[j + 1024];
        bo4[nt] = b_ih[j + 1536] + b_hh[j + 1536];
        cti[nt] = g_ctx[(size_t)bglob * (3 * Hsz) + j];
        ctf[nt] = g_ctx[(size_t)bglob * (3 * Hsz) + j + 512];
        cto[nt] = g_ctx[(size_t)bglob * (3 * Hsz) + j + 1024];
        creg[nt] = 0.f;
        const int hc = j >> 5, kj = j & 31, s4h = kj >> 3, eh = kj & 7;
        hoff[nt] = (uint32_t)(mg * 16 + hc) * 8192 + (s4h >> 1) * 2048 + (eh << 1)
                 + (uint32_t)rowc * 32
                 + ((((unsigned)s4h ^ ((unsigned)rowc >> 2)) & 1u) << 4);
    }

    unsigned phbits = 0;
    int bar_t = 0;   // highest step whose h-barrier we've confirmed

    // producer fill: 16KB stage = two 8KB k32 sub-images
    auto fill = [&](int gc) {
        const int tp = gc / CPS, cc = gc % CPS;
        const int s3 = gc % 3;
        if (cc >= 2 && tp > bar_t) {
            const unsigned tgt = 256u * (unsigned)tp;   // 32 blocks x 8 warps per step
            unsigned v;
            do {
                asm volatile("ld.global.acquire.gpu.u32 %0, [%1];" : "=r"(v) : "l"(&g_barm[mg]));
                if (v >= tgt) break;
                __nanosleep(32);
            } while (true);
            bar_t = tp;
        }
        const unsigned char* src = (cc < 2)
            ? g_ximg + ((size_t)(tp * 4 + mg) * 4 + 2 * cc) * 8192
            : g_himg[tp & 1] + (size_t)(mg * 16 + (2 * cc - 4)) * 8192;
        MBARRIER_EXPECT_TX(mb0 + s3 * 8, 16384u);
        bulk_g2s(sb + ABASE + s3 * 16384,        src,        8192u, mb0 + s3 * 8);
        bulk_g2s(sb + ABASE + s3 * 16384 + 8192, src + 8192, 8192u, mb0 + s3 * 8);
    };

    if (tid == 0) { fill(0); fill(1); }

#pragma unroll 1
    for (int t = 0; t < Ssz; t++) {
        float acc[4][4];
#pragma unroll
        for (int i = 0; i < 4; i++)
#pragma unroll
            for (int q = 0; q < 4; q++) acc[i][q] = 0.f;

#pragma unroll 1
        for (int c = 0; c < CPS; c++) {
            const int gc = t * CPS + c;
            const int s3 = gc % 3;
            MBARRIER_WAIT_PARITY(mb0 + s3 * 8, (phbits >> s3) & 1u);
            phbits ^= (1u << s3);
            __syncthreads();
            if (tid == 0 && gc + 2 < Ssz * CPS) fill(gc + 2);

            const uint32_t st = sb + ABASE + s3 * 16384;
#pragma unroll
            for (int sub = 0; sub < 2; sub++) {
                const int oc = 2 * c + sub;         // k32 chunk index 0..19
                const uint32_t ast = st + sub * 8192;
                const uint32_t wst = sb + oc * 4096;
#pragma unroll
                for (int kb = 0; kb < 2; kb++) {
                    uint32_t a0, a1, a2, a3, l0, l1, l2, l3;
                    LDSM4(a0, a1, a2, a3, ast + kb * 2048 + offA);
                    LDSM4(l0, l1, l2, l3, ast + 4096 + kb * 2048 + offA);
                    uint32_t bh0, bh1, bh2, bh3, bh4, bh5, bh6, bh7;
                    LDSM4(bh0, bh1, bh2, bh3, wst + WHI_OFF + kb * 2048 + offB);
                    LDSM4(bh4, bh5, bh6, bh7, wst + WHI_OFF + kb * 2048 + offB + 512);
                    uint32_t bl0, bl1, bl2, bl3, bl4, bl5, bl6, bl7;
                    LDSM4(bl0, bl1, bl2, bl3, wst + WLO_OFF + kb * 2048 + offB);
                    LDSM4(bl4, bl5, bl6, bl7, wst + WLO_OFF + kb * 2048 + offB + 512);

                    MMA(acc[0], a0, a1, a2, a3, bh0, bh1);
                    MMA(acc[1], a0, a1, a2, a3, bh2, bh3);
                    MMA(acc[2], a0, a1, a2, a3, bh4, bh5);
                    MMA(acc[3], a0, a1, a2, a3, bh6, bh7);
                    MMA(acc[0], l0, l1, l2, l3, bh0, bh1);
                    MMA(acc[1], l0, l1, l2, l3, bh2, bh3);
                    MMA(acc[2], l0, l1, l2, l3, bh4, bh5);
                    MMA(acc[3], l0, l1, l2, l3, bh6, bh7);
                    MMA(acc[0], a0, a1, a2, a3, bl0, bl1);
                    MMA(acc[1], a0, a1, a2, a3, bl2, bl3);
                    MMA(acc[2], a0, a1, a2, a3, bl4, bl5);
                    MMA(acc[3], a0, a1, a2, a3, bl6, bl7);
                }
            }
        }

        // ---- shuffle epilogue: no smem, no block sync ----
        unsigned char* himg = g_himg[(t + 1) & 1];
        const bool oddq = (lane & 1);
#pragma unroll
        for (int nt = 0; nt < 4; nt++) {
            float x0 = __shfl_xor_sync(0xffffffffu, acc[nt][0], 1);
            float x1 = __shfl_xor_sync(0xffffffffu, acc[nt][1], 1);
            float x2 = __shfl_xor_sync(0xffffffffu, acc[nt][2], 1);
            float x3 = __shfl_xor_sync(0xffffffffu, acc[nt][3], 1);
            float g0, g1, g2, g3;
            if (!oddq) { g0 = acc[nt][0]; g1 = acc[nt][1]; g2 = x0; g3 = x1; }
            else       { g0 = x2; g1 = x3; g2 = acc[nt][2]; g3 = acc[nt][3]; }
            float iv = sigmoidf_(g0 + bi[nt])  * cti[nt];
            float fv = sigmoidf_(g1 + bf4[nt]) * ctf[nt];
            float gg = tanhf_(g2 + bg4[nt]);
            float ov = sigmoidf_(g3 + bo4[nt]) * cto[nt];
            float cn = fv * creg[nt] + iv * gg;
            creg[nt] = cn;
            float hn = ov * tanhf_(cn);
            __nv_bfloat16 hb = __float2bfloat16(hn);
            *(__nv_bfloat16*)(himg + hoff[nt])        = hb;
            *(__nv_bfloat16*)(himg + hoff[nt] + 4096) = __float2bfloat16(hn - __bfloat162float(hb));
            if (t == Ssz - 1) g_h[bglob * Hsz + jc[nt]] = hn;
        }

        // warp-granularity release arrival on this m-group's counter
        __syncwarp();
        if (lane == 0) {
            __threadfence();
            atomicAdd(&g_barm[mg], 1u);
        }
    }
}

// ---------------- mu / log_var / z ----------------
__global__ __launch_bounds__(512) void mulv_kernel(
    const float* __restrict__ mu_w, const float* __restrict__ mu_b,
    const float* __restrict__ lv_w, const float* __restrict__ lv_b,
    const float* __restrict__ eps, float* __restrict__ out)
{
    const int b = blockIdx.x;
    const int tid = threadIdx.x;
    __shared__ float sh[512];
    __shared__ float smu[16], slv[16];

    sh[tid] = g_h[b * Hsz + tid];
    __syncthreads();

    const int w = tid >> 5, lane = tid & 31;
    const int l = w;
    float sm = 0.f, sl = 0.f;
    for (int k = lane; k < Hsz; k += 32) {
        float hv = sh[k];
        sm += hv * mu_w[k * Lsz + l];
        sl += hv * lv_w[k * Lsz + l];
    }
#pragma unroll
    for (int o = 16; o > 0; o >>= 1) {
        sm += __shfl_down_sync(0xffffffffu, sm, o);
        sl += __shfl_down_sync(0xffffffffu, sl, o);
    }
    if (lane == 0) { smu[l] = sm; slv[l] = sl; }
    __syncthreads();

    if (tid < Lsz) {
        float mu = smu[tid] + mu_b[tid];
        float lv = slv[tid] + lv_b[tid];
        out[Bsz * Fsz + b * Lsz + tid] = mu;
        out[Bsz * Fsz + Bsz * Lsz + b * Lsz + tid] = lv;
        g_z[b * Lsz + tid] = mu + eps[b * Lsz + tid] * expf(0.5f * lv);
    }
}

// ---------------- decoder ----------------
__global__ __launch_bounds__(128) void dec_kernel(
    const float* __restrict__ dec_w1, const float* __restrict__ dec_b1,
    const float* __restrict__ dec_w2, const float* __restrict__ dec_b2,
    float* __restrict__ out)
{
    const int b = blockIdx.x;
    const int tid = threadIdx.x;
    __shared__ float sz[16];
    __shared__ float st[512];

    if (tid < 16) sz[tid] = g_z[b * Lsz + tid];
    __syncthreads();

#pragma unroll
    for (int u = 0; u < 4; u++) {
        int jj = tid + u * 128;
        float s = dec_b1[jj];
#pragma unroll
        for (int k = 0; k < 16; k++) s += sz[k] * dec_w1[k * Hsz + jj];
        st[jj] = fmaxf(s, 0.f);
    }
    __syncthreads();

    float r = dec_b2[tid];
    for (int k = 0; k < Hsz; k++) r += st[k] * dec_w2[k * Fsz + tid];
    out[b * Fsz + tid] = r;
}

// ---------------- launch ----------------
extern "C" void kernel_launch(void* const* d_in, const int* in_sizes, int n_in,
                              void* d_out, int out_size)
{
    const float* x       = (const float*)d_in[0];
    const float* context = (const float*)d_in[1];
    const float* eps     = (const float*)d_in[2];
    const float* W_ih    = (const float*)d_in[3];
    const float* b_ih    = (const float*)d_in[4];
    const float* W_hh    = (const float*)d_in[5];
    const float* b_hh    = (const float*)d_in[6];
    const float* cg_w1   = (const float*)d_in[7];
    const float* cg_b1   = (const float*)d_in[8];
    const float* cg_w2   = (const float*)d_in[9];
    const float* cg_b2   = (const float*)d_in[10];
    const float* mu_w    = (const float*)d_in[11];
    const float* mu_b    = (const float*)d_in[12];
    const float* lv_w    = (const float*)d_in[13];
    const float* lv_b    = (const float*)d_in[14];
    const float* dec_w1  = (const float*)d_in[15];
    const float* dec_b1  = (const float*)d_in[16];
    const float* dec_w2  = (const float*)d_in[17];
    const float* dec_b2  = (const float*)d_in[18];
    float* out = (float*)d_out;

    static int smem_set = 0;
    if (!smem_set) {
        cudaFuncSetAttribute(lstm_persist, cudaFuncAttributeMaxDynamicSharedMemorySize,
                             SMEM_PERSIST);
        smem_set = 1;
    }

    init_kernel<<<(4 * 16 * 8192 / 8 + 511) / 512, 512>>>();
    wsplit_kernel<<<2048, 128>>>(W_ih, W_hh);
    wimg_kernel<<<32, 256>>>();
    xsplit_kernel<<<(Bsz * Ssz * Fsz) / (256 * 4), 256>>>(x);
    ximg_kernel<<<512, 256>>>();

    ctx_gemm_kernel<<<dim3(8, 4), 256>>>(context, cg_w1, cg_b1, 0);
    ctx_gemm_kernel<<<dim3(24, 4), 256>>>(nullptr, cg_w2, cg_b2, 1);

    lstm_persist<<<128, 256, SMEM_PERSIST>>>(b_ih, b_hh);

    mulv_kernel<<<Bsz, 512>>>(mu_w, mu_b, lv_w, lv_b, eps, out);
    dec_kernel<<<Bsz, 128>>>(dec_w1, dec_b1, dec_w2, dec_b2, out);
}

// round 8
// speedup vs baseline: 4.2795x; 1.0676x over previous
#include <cuda_runtime.h>
#include <cuda_bf16.h>
#include <math.h>
#include <stdint.h>

#define Bsz 256
#define Ssz 128
#define Fsz 128
#define Hsz 512
#define G4H 2048
#define Csz 64
#define Lsz 16
#define CPS 10            // k64 chunks per step (K=640)
#define NSTG 4            // pipeline stages

// persistent-kernel smem layout
#define WHI_OFF 0                   // resident W hi: 20 x 4KB (k32 granularity)
#define WLO_OFF 81920               // resident W lo: 20 x 4KB
#define ABASE   163840              // 4 stages x 16KB
#define MB_OFF  (ABASE + NSTG * 16384)   // full[4] @ +0..31, empty[4] @ +32..63, W @ +64
#define SMEM_PERSIST (MB_OFF + 80)       // 229456

// ---------------- device scratch ----------------
__device__ float g_h[Bsz * Hsz];        // final h (fp32) for mulv
__device__ float g_ctx[Bsz * 3 * Hsz];
__device__ float g_t1[Bsz * Hsz];
__device__ float g_z[Bsz * Lsz];
__device__ unsigned int g_hflag[4][16]; // per (mgroup, k32 h-chunk) warp-arrival counters
__device__ __nv_bfloat16 g_wh[2048 * 640];
__device__ __nv_bfloat16 g_wl[2048 * 640];
// byte-exact smem images for bulk copies
__device__ unsigned char g_wimg[32 * 163840];              // per n-slice: [hi 20x4KB][lo 20x4KB]
__device__ unsigned char g_ximg[128 * 4 * 4 * 8192];       // [t][mgrp][k32-chunk 0-3][8KB]
__device__ unsigned char g_himg[2][4 * 16 * 8192];         // [par][mgrp][k32-chunk 4-19][8KB]

__device__ __forceinline__ float sigmoidf_(float v) {
    return __fdividef(1.0f, 1.0f + __expf(-v));
}
__device__ __forceinline__ float tanhf_(float v) {
    float vc = fminf(fmaxf(v, -15.0f), 15.0f);
    float e = __expf(2.0f * vc);
    return __fdividef(e - 1.0f, e + 1.0f);
}

__device__ __forceinline__ uint32_t smem_to_u32(const void* p) {
    uint32_t a;
    asm("{ .reg .u64 t; cvta.to.shared.u64 t, %1; cvt.u32.u64 %0, t; }" : "=r"(a) : "l"(p));
    return a;
}

#define MBARRIER_INIT(addr, cnt) \
    asm volatile("mbarrier.init.shared.b64 [%0], %1;" :: "r"((uint32_t)(addr)), "r"((uint32_t)(cnt)) : "memory")
#define MBARRIER_ARRIVE(addr) \
    asm volatile("mbarrier.arrive.shared.b64 _, [%0];" :: "r"((uint32_t)(addr)) : "memory")
#define MBARRIER_EXPECT_TX(addr, bytes) \
    asm volatile("mbarrier.arrive.expect_tx.shared.b64 _, [%0], %1;" :: "r"((uint32_t)(addr)), "r"((uint32_t)(bytes)) : "memory")
#define MBARRIER_WAIT_PARITY(mbar_smem_addr, phase_parity) do { \
    uint32_t _mbar = (uint32_t)(mbar_smem_addr); \
    uint32_t _parity = (uint32_t)(phase_parity); \
    uint32_t _done; \
    asm volatile("{\n\t.reg .pred p;\n\t" \
        "mbarrier.try_wait.parity.acquire.cta.shared::cta.b64 p, [%1], %2;\n\t" \
        "selp.b32 %0, 1, 0, p;\n\t}" \
        : "=r"(_done) : "r"(_mbar), "r"(_parity) : "memory"); \
    if (!_done) { \
        asm volatile("{\n\t.reg .pred P1;\n\t" \
            "WAIT_LOOP_%=:\n\t" \
            "mbarrier.try_wait.parity.acquire.cta.shared::cta.b64 P1, [%0], %1, 0x989680;\n\t" \
            "@P1 bra.uni WAIT_DONE_%=;\n\t" \
            "bra.uni WAIT_LOOP_%=;\n\t" \
            "WAIT_DONE_%=:\n\t}" \
            :: "r"(_mbar), "r"(_parity) : "memory"); \
    } \
} while (0)
#define FENCE_ASYNC_SHARED() asm volatile("fence.proxy.async.shared::cta;" ::: "memory")

__device__ __forceinline__ void bulk_g2s(uint32_t dst, const void* src, uint32_t bytes, uint32_t mbar) {
    asm volatile("cp.async.bulk.shared::cluster.global.mbarrier::complete_tx::bytes [%0], [%1], %2, [%3];"
                 :: "r"(dst), "l"(src), "r"(bytes), "r"(mbar) : "memory");
}

#define LDSM4(r0, r1, r2, r3, a) \
    asm volatile("ldmatrix.sync.aligned.m8n8.x4.shared.b16 {%0,%1,%2,%3}, [%4];" \
                 : "=r"(r0), "=r"(r1), "=r"(r2), "=r"(r3) : "r"(a))

#define MMA(c, a0, a1, a2, a3, b0, b1) \
    asm volatile("mma.sync.aligned.m16n8k16.row.col.f32.bf16.bf16.f32 " \
                 "{%0,%1,%2,%3}, {%4,%5,%6,%7}, {%8,%9}, {%0,%1,%2,%3};" \
                 : "+f"((c)[0]), "+f"((c)[1]), "+f"((c)[2]), "+f"((c)[3]) \
                 : "r"(a0), "r"(a1), "r"(a2), "r"(a3), "r"(b0), "r"(b1))

__device__ __forceinline__ void bsplit(float v, unsigned short& h, unsigned short& l) {
    __nv_bfloat16 bh = __float2bfloat16(v);
    float r = v - __bfloat162float(bh);
    __nv_bfloat16 bl = __float2bfloat16(r);
    h = *(unsigned short*)&bh;
    l = *(unsigned short*)&bl;
}

// ---------------- init: zero h0 images + flags ----------------
__global__ void init_kernel() {
    int i = blockIdx.x * blockDim.x + threadIdx.x;
    if (i < 64) ((unsigned int*)g_hflag)[i] = 0u;
    if (i < (4 * 16 * 8192) / 8) ((unsigned long long*)g_himg[0])[i] = 0ull;
}

// ---------------- W split: [k][2048] fp32 -> [n][640] bf16 hi/lo ----------------
__global__ __launch_bounds__(128) void wsplit_kernel(
    const float* __restrict__ W_ih, const float* __restrict__ W_hh)
{
    const int n = blockIdx.x;
    const int j = n >> 2, g = n & 3;
    const int col = g * Hsz + j;
    for (int k = threadIdx.x; k < 640; k += 128) {
        float v = (k < Fsz) ? W_ih[k * G4H + col] : W_hh[(k - Fsz) * G4H + col];
        unsigned short h, l;
        bsplit(v, h, l);
        ((unsigned short*)g_wh)[n * 640 + k] = h;
        ((unsigned short*)g_wl)[n * 640 + k] = l;
    }
}

// ---------------- W image pack ----------------
__global__ __launch_bounds__(256) void wimg_kernel() {
    const int ns = blockIdx.x;
    const int cr = threadIdx.x >> 2, s4 = threadIdx.x & 3;
    const int n = ns * 64 + cr;
    const uint32_t seg = (s4 >> 1) * 2048 + cr * 32 + (((s4) ^ (cr >> 2)) & 1) * 16;
    unsigned char* base = g_wimg + (size_t)ns * 163840;
#pragma unroll 1
    for (int c = 0; c < 20; c++) {
        const size_t srco = (size_t)n * 640 + c * 32 + s4 * 8;
        *(uint4*)(base + c * 4096 + seg)         = *(const uint4*)(g_wh + srco);
        *(uint4*)(base + 81920 + c * 4096 + seg) = *(const uint4*)(g_wl + srco);
    }
}

// ---------------- x image pack (fused split + pack, reads x fp32 directly) ----------------
__global__ __launch_bounds__(256) void ximg_kernel(const float* __restrict__ x) {
    const int bid = blockIdx.x;                   // 0..511
    const int t = bid >> 2, mg = bid & 3;
    const int cr = threadIdx.x >> 2, s4 = threadIdx.x & 3;
    const int b = mg * 64 + cr;
    const uint32_t seg = (s4 >> 1) * 2048 + cr * 32 + (((s4) ^ (cr >> 2)) & 1) * 16;
    unsigned char* base = g_ximg + (size_t)(t * 4 + mg) * 4 * 8192;
#pragma unroll
    for (int c = 0; c < 4; c++) {
        const float* src = x + (size_t)b * (Ssz * Fsz) + (size_t)t * Fsz + c * 32 + s4 * 8;
        float4 v0 = *(const float4*)src;
        float4 v1 = *(const float4*)(src + 4);
        unsigned short h[8], l[8];
        bsplit(v0.x, h[0], l[0]); bsplit(v0.y, h[1], l[1]);
        bsplit(v0.z, h[2], l[2]); bsplit(v0.w, h[3], l[3]);
        bsplit(v1.x, h[4], l[4]); bsplit(v1.y, h[5], l[5]);
        bsplit(v1.z, h[6], l[6]); bsplit(v1.w, h[7], l[7]);
        uint4 hp, lp;
        hp.x = (uint32_t)h[0] | ((uint32_t)h[1] << 16);
        hp.y = (uint32_t)h[2] | ((uint32_t)h[3] << 16);
        hp.z = (uint32_t)h[4] | ((uint32_t)h[5] << 16);
        hp.w = (uint32_t)h[6] | ((uint32_t)h[7] << 16);
        lp.x = (uint32_t)l[0] | ((uint32_t)l[1] << 16);
        lp.y = (uint32_t)l[2] | ((uint32_t)l[3] << 16);
        lp.z = (uint32_t)l[4] | ((uint32_t)l[5] << 16);
        lp.w = (uint32_t)l[6] | ((uint32_t)l[7] << 16);
        *(uint4*)(base + c * 8192 + seg)        = hp;
        *(uint4*)(base + c * 8192 + 4096 + seg) = lp;
    }
}

// ---------------- context-gate GEMMs ----------------
__global__ __launch_bounds__(256) void ctx_gemm_kernel(
    const float* __restrict__ Aext, const float* __restrict__ W,
    const float* __restrict__ bias, int mode)
{
    const int K   = (mode == 0) ? 64 : 512;
    const int lda = (mode == 0) ? 64 : 512;
    const int ldw = (mode == 0) ? 512 : 1536;
    const int ldc = ldw;
    const float* A = (mode == 0) ? Aext : g_t1;
    float* Cout    = (mode == 0) ? g_t1 : g_ctx;

    const int n0 = blockIdx.x * 64;
    const int m0 = blockIdx.y * 64;
    const int tid = threadIdx.x;
    const int tc = tid & 15;
    const int rg = tid >> 4;

    __shared__ float As[16][68];
    __shared__ float Ws[16][68];

    float4 acc[4];
#pragma unroll
    for (int i = 0; i < 4; i++) acc[i] = make_float4(0.f, 0.f, 0.f, 0.f);

    for (int k0 = 0; k0 < K; k0 += 16) {
#pragma unroll
        for (int u = 0; u < 4; u++) {
            int i = tid + u * 256;
            int r = i >> 4, kk = i & 15;
            As[kk][r] = A[(m0 + r) * lda + k0 + kk];
            int kr = i >> 6, c = i & 63;
            Ws[kr][c] = W[(k0 + kr) * ldw + n0 + c];
        }
        __syncthreads();
#pragma unroll
        for (int kk = 0; kk < 16; kk++) {
            float4 w = *(const float4*)&Ws[kk][tc * 4];
            float4 a = *(const float4*)&As[kk][rg * 4];
            acc[0].x += a.x * w.x; acc[0].y += a.x * w.y; acc[0].z += a.x * w.z; acc[0].w += a.x * w.w;
            acc[1].x += a.y * w.x; acc[1].y += a.y * w.y; acc[1].z += a.y * w.z; acc[1].w += a.y * w.w;
            acc[2].x += a.z * w.x; acc[2].y += a.z * w.y; acc[2].z += a.z * w.z; acc[2].w += a.z * w.w;
            acc[3].x += a.w * w.x; acc[3].y += a.w * w.y; acc[3].z += a.w * w.z; acc[3].w += a.w * w.w;
        }
        __syncthreads();
    }

    int col = n0 + tc * 4;
    float4 bv = *(const float4*)&bias[col];
#pragma unroll
    for (int ri = 0; ri < 4; ri++) {
        int row = m0 + rg * 4 + ri;
        float4 v = acc[ri];
        v.x += bv.x; v.y += bv.y; v.z += bv.z; v.w += bv.w;
        if (mode == 0) {
            v.x = fmaxf(v.x, 0.f); v.y = fmaxf(v.y, 0.f);
            v.z = fmaxf(v.z, 0.f); v.w = fmaxf(v.w, 0.f);
        } else {
            v.x = sigmoidf_(v.x); v.y = sigmoidf_(v.y);
            v.z = sigmoidf_(v.z); v.w = sigmoidf_(v.w);
        }
        *(float4*)&Cout[row * ldc + col] = v;
    }
}

// ---------------- persistent LSTM: producer-warp pipeline, no block syncs ----------------
// 288 threads: warps 0-7 consume (MMA + epilogue), warp 8 lane 0 produces (bulk fills).
__global__ __launch_bounds__(288, 1) void lstm_persist(
    const float* __restrict__ b_ih, const float* __restrict__ b_hh)
{
    extern __shared__ char smbuf[];
    const uint32_t sb = smem_to_u32(smbuf);
    const int tid = threadIdx.x;
    const int lane = tid & 31, wid = tid >> 5;
    const int bx = blockIdx.x;
    const int nsl = bx & 31;
    const int n0 = nsl * 64, j0 = nsl * 16;
    const int mg = bx >> 5;
    const int m0 = mg * 64;

    const uint32_t mbF = sb + MB_OFF;         // full[s] at +s*8
    const uint32_t mbE = sb + MB_OFF + 32;    // empty[s] at +s*8
    const uint32_t mbW = sb + MB_OFF + 64;

    if (tid == 0) {
#pragma unroll
        for (int s = 0; s < NSTG; s++) {
            MBARRIER_INIT(mbF + s * 8, 1);
            MBARRIER_INIT(mbE + s * 8, 8);
        }
        MBARRIER_INIT(mbW, 1);
    }
    FENCE_ASYNC_SHARED();
    __syncthreads();

    // ---- resident W slice: one-shot bulk load ----
    if (tid == 0) {
        MBARRIER_EXPECT_TX(mbW, 163840u);
        const unsigned char* src = g_wimg + (size_t)nsl * 163840;
#pragma unroll
        for (int i = 0; i < 10; i++)
            bulk_g2s(sb + i * 16384, src + i * 16384, 16384u, mbW);
    }
    MBARRIER_WAIT_PARITY(mbW, 0);
    __syncthreads();

    if (wid == 8) {
        // ================= producer =================
        if (lane == 0) {
            unsigned eph = 0xFu;     // empty parities start at 1 (first wait passes)
#pragma unroll 1
            for (int gc = 0; gc < Ssz * CPS; gc++) {
                const int s = gc & 3;
                MBARRIER_WAIT_PARITY(mbE + s * 8, (eph >> s) & 1u);
                eph ^= (1u << s);
                const int tp = gc / CPS, cc = gc % CPS;
                const unsigned char* src;
                if (cc < 2) {
                    src = g_ximg + ((size_t)(tp * 4 + mg) * 4 + 2 * cc) * 8192;
                } else {
                    if (tp > 0) {
                        const unsigned tgt = 16u * (unsigned)tp;
                        const int hc = 2 * cc - 4;
#pragma unroll
                        for (int q = 0; q < 2; q++) {
                            unsigned v;
                            do {
                                asm volatile("ld.global.acquire.gpu.u32 %0, [%1];"
                                             : "=r"(v) : "l"(&g_hflag[mg][hc + q]));
                                if (v >= tgt) break;
                                __nanosleep(32);
                            } while (true);
                        }
                    }
                    src = g_himg[tp & 1] + (size_t)(mg * 16 + (2 * cc - 4)) * 8192;
                }
                MBARRIER_EXPECT_TX(mbF + s * 8, 16384u);
                bulk_g2s(sb + ABASE + s * 16384,        src,        8192u, mbF + s * 8);
                bulk_g2s(sb + ABASE + s * 16384 + 8192, src + 8192, 8192u, mbF + s * 8);
            }
        }
        return;
    }

    // ================= consumers (warps 0-7) =================
    const int m0w = (wid >> 1) * 16;
    const int n0w = (wid & 1) * 32;
    const int rA = m0w + (lane & 15);
    const uint32_t offA = rA * 32 + ((((lane >> 4) ^ (rA >> 2)) & 1) << 4);
    const int rB = n0w + ((lane >> 4) << 3) + (lane & 7);
    const uint32_t offB = rB * 32 + ((((lane >> 3) ^ (rB >> 2)) & 1) << 4);

    // per-cell persistent registers (fragment layout)
    const int rowc = m0w + (lane >> 2) + (lane & 1) * 8;
    const int bglob = m0 + rowc;
    int jc[4];
    float bi[4], bf4[4], bg4[4], bo4[4];
    float creg[4], cti[4], ctf[4], cto[4];
    uint32_t hoff[4];
#pragma unroll
    for (int nt = 0; nt < 4; nt++) {
        const int j = j0 + (n0w >> 2) + nt * 2 + ((lane >> 1) & 1);
        jc[nt] = j;
        bi[nt]  = b_ih[j]        + b_hh[j];
        bf4[nt] = b_ih[j + 512]  + b_hh[j + 512];
        bg4[nt] = b_ih[j + 1024] + b_hh[j + 1024];
        bo4[nt] = b_ih[j + 1536] + b_hh[j + 1536];
        cti[nt] = g_ctx[(size_t)bglob * (3 * Hsz) + j];
        ctf[nt] = g_ctx[(size_t)bglob * (3 * Hsz) + j + 512];
        cto[nt] = g_ctx[(size_t)bglob * (3 * Hsz) + j + 1024];
        creg[nt] = 0.f;
        const int hc = j >> 5, kj = j & 31, s4h = kj >> 3, eh = kj & 7;
        hoff[nt] = (uint32_t)(mg * 16 + hc) * 8192 + (s4h >> 1) * 2048 + (eh << 1)
                 + (uint32_t)rowc * 32
                 + ((((unsigned)s4h ^ ((unsigned)rowc >> 2)) & 1u) << 4);
    }

    unsigned fph = 0;

#pragma unroll 1
    for (int t = 0; t < Ssz; t++) {
        float acc[4][4];
#pragma unroll
        for (int i = 0; i < 4; i++)
#pragma unroll
            for (int q = 0; q < 4; q++) acc[i][q] = 0.f;

#pragma unroll 1
        for (int c = 0; c < CPS; c++) {
            const int gc = t * CPS + c;
            const int s = gc & 3;
            MBARRIER_WAIT_PARITY(mbF + s * 8, (fph >> s) & 1u);
            fph ^= (1u << s);

            const uint32_t st = sb + ABASE + s * 16384;
#pragma unroll
            for (int sub = 0; sub < 2; sub++) {
                const int oc = 2 * c + sub;
                const uint32_t ast = st + sub * 8192;
                const uint32_t wst = sb + oc * 4096;
#pragma unroll
                for (int kb = 0; kb < 2; kb++) {
                    uint32_t a0, a1, a2, a3, l0, l1, l2, l3;
                    LDSM4(a0, a1, a2, a3, ast + kb * 2048 + offA);
                    LDSM4(l0, l1, l2, l3, ast + 4096 + kb * 2048 + offA);
                    uint32_t bh0, bh1, bh2, bh3, bh4, bh5, bh6, bh7;
                    LDSM4(bh0, bh1, bh2, bh3, wst + WHI_OFF + kb * 2048 + offB);
                    LDSM4(bh4, bh5, bh6, bh7, wst + WHI_OFF + kb * 2048 + offB + 512);
                    uint32_t bl0, bl1, bl2, bl3, bl4, bl5, bl6, bl7;
                    LDSM4(bl0, bl1, bl2, bl3, wst + WLO_OFF + kb * 2048 + offB);
                    LDSM4(bl4, bl5, bl6, bl7, wst + WLO_OFF + kb * 2048 + offB + 512);

                    MMA(acc[0], a0, a1, a2, a3, bh0, bh1);
                    MMA(acc[1], a0, a1, a2, a3, bh2, bh3);
                    MMA(acc[2], a0, a1, a2, a3, bh4, bh5);
                    MMA(acc[3], a0, a1, a2, a3, bh6, bh7);
                    MMA(acc[0], l0, l1, l2, l3, bh0, bh1);
                    MMA(acc[1], l0, l1, l2, l3, bh2, bh3);
                    MMA(acc[2], l0, l1, l2, l3, bh4, bh5);
                    MMA(acc[3], l0, l1, l2, l3, bh6, bh7);
                    MMA(acc[0], a0, a1, a2, a3, bl0, bl1);
                    MMA(acc[1], a0, a1, a2, a3, bl2, bl3);
                    MMA(acc[2], a0, a1, a2, a3, bl4, bl5);
                    MMA(acc[3], a0, a1, a2, a3, bl6, bl7);
                }
            }
            if (lane == 0) MBARRIER_ARRIVE(mbE + s * 8);
        }

        // ---- shuffle epilogue ----
        unsigned char* himg = g_himg[(t + 1) & 1];
        const bool oddq = (lane & 1);
#pragma unroll
        for (int nt = 0; nt < 4; nt++) {
            float x0 = __shfl_xor_sync(0xffffffffu, acc[nt][0], 1);
            float x1 = __shfl_xor_sync(0xffffffffu, acc[nt][1], 1);
            float x2 = __shfl_xor_sync(0xffffffffu, acc[nt][2], 1);
            float x3 = __shfl_xor_sync(0xffffffffu, acc[nt][3], 1);
            float g0, g1, g2, g3;
            if (!oddq) { g0 = acc[nt][0]; g1 = acc[nt][1]; g2 = x0; g3 = x1; }
            else       { g0 = x2; g1 = x3; g2 = acc[nt][2]; g3 = acc[nt][3]; }
            float iv = sigmoidf_(g0 + bi[nt])  * cti[nt];
            float fv = sigmoidf_(g1 + bf4[nt]) * ctf[nt];
            float gg = tanhf_(g2 + bg4[nt]);
            float ov = sigmoidf_(g3 + bo4[nt]) * cto[nt];
            float cn = fv * creg[nt] + iv * gg;
            creg[nt] = cn;
            float hn = ov * tanhf_(cn);
            __nv_bfloat16 hb = __float2bfloat16(hn);
            *(__nv_bfloat16*)(himg + hoff[nt])        = hb;
            *(__nv_bfloat16*)(himg + hoff[nt] + 4096) = __float2bfloat16(hn - __bfloat162float(hb));
            if (t == Ssz - 1) g_h[bglob * Hsz + jc[nt]] = hn;
        }

        // warp-granularity release arrival on this block's h-chunk flag
        __syncwarp();
        if (lane == 0) {
            __threadfence();
            atomicAdd(&g_hflag[mg][nsl >> 1], 1u);
        }
    }
}

// ---------------- mu / log_var / z ----------------
__global__ __launch_bounds__(512) void mulv_kernel(
    const float* __restrict__ mu_w, const float* __restrict__ mu_b,
    const float* __restrict__ lv_w, const float* __restrict__ lv_b,
    const float* __restrict__ eps, float* __restrict__ out)
{
    const int b = blockIdx.x;
    const int tid = threadIdx.x;
    __shared__ float sh[512];
    __shared__ float smu[16], slv[16];

    sh[tid] = g_h[b * Hsz + tid];
    __syncthreads();

    const int w = tid >> 5, lane = tid & 31;
    const int l = w;
    float sm = 0.f, sl = 0.f;
    for (int k = lane; k < Hsz; k += 32) {
        float hv = sh[k];
        sm += hv * mu_w[k * Lsz + l];
        sl += hv * lv_w[k * Lsz + l];
    }
#pragma unroll
    for (int o = 16; o > 0; o >>= 1) {
        sm += __shfl_down_sync(0xffffffffu, sm, o);
        sl += __shfl_down_sync(0xffffffffu, sl, o);
    }
    if (lane == 0) { smu[l] = sm; slv[l] = sl; }
    __syncthreads();

    if (tid < Lsz) {
        float mu = smu[tid] + mu_b[tid];
        float lv = slv[tid] + lv_b[tid];
        out[Bsz * Fsz + b * Lsz + tid] = mu;
        out[Bsz * Fsz + Bsz * Lsz + b * Lsz + tid] = lv;
        g_z[b * Lsz + tid] = mu + eps[b * Lsz + tid] * expf(0.5f * lv);
    }
}

// ---------------- decoder ----------------
__global__ __launch_bounds__(128) void dec_kernel(
    const float* __restrict__ dec_w1, const float* __restrict__ dec_b1,
    const float* __restrict__ dec_w2, const float* __restrict__ dec_b2,
    float* __restrict__ out)
{
    const int b = blockIdx.x;
    const int tid = threadIdx.x;
    __shared__ float sz[16];
    __shared__ float st[512];

    if (tid < 16) sz[tid] = g_z[b * Lsz + tid];
    __syncthreads();

#pragma unroll
    for (int u = 0; u < 4; u++) {
        int jj = tid + u * 128;
        float s = dec_b1[jj];
#pragma unroll
        for (int k = 0; k < 16; k++) s += sz[k] * dec_w1[k * Hsz + jj];
        st[jj] = fmaxf(s, 0.f);
    }
    __syncthreads();

    float r = dec_b2[tid];
    for (int k = 0; k < Hsz; k++) r += st[k] * dec_w2[k * Fsz + tid];
    out[b * Fsz + tid] = r;
}

// ---------------- launch ----------------
extern "C" void kernel_launch(void* const* d_in, const int* in_sizes, int n_in,
                              void* d_out, int out_size)
{
    const float* x       = (const float*)d_in[0];
    const float* context = (const float*)d_in[1];
    const float* eps     = (const float*)d_in[2];
    const float* W_ih    = (const float*)d_in[3];
    const float* b_ih    = (const float*)d_in[4];
    const float* W_hh    = (const float*)d_in[5];
    const float* b_hh    = (const float*)d_in[6];
    const float* cg_w1   = (const float*)d_in[7];
    const float* cg_b1   = (const float*)d_in[8];
    const float* cg_w2   = (const float*)d_in[9];
    const float* cg_b2   = (const float*)d_in[10];
    const float* mu_w    = (const float*)d_in[11];
    const float* mu_b    = (const float*)d_in[12];
    const float* lv_w    = (const float*)d_in[13];
    const float* lv_b    = (const float*)d_in[14];
    const float* dec_w1  = (const float*)d_in[15];
    const float* dec_b1  = (const float*)d_in[16];
    const float* dec_w2  = (const float*)d_in[17];
    const float* dec_b2  = (const float*)d_in[18];
    float* out = (float*)d_out;

    static int smem_set = 0;
    if (!smem_set) {
        cudaFuncSetAttribute(lstm_persist, cudaFuncAttributeMaxDynamicSharedMemorySize,
                             SMEM_PERSIST);
        smem_set = 1;
    }

    init_kernel<<<(4 * 16 * 8192 / 8 + 511) / 512, 512>>>();
    wsplit_kernel<<<2048, 128>>>(W_ih, W_hh);
    wimg_kernel<<<32, 256>>>();
    ximg_kernel<<<512, 256>>>(x);

    ctx_gemm_kernel<<<dim3(8, 4), 256>>>(context, cg_w1, cg_b1, 0);
    ctx_gemm_kernel<<<dim3(24, 4), 256>>>(nullptr, cg_w2, cg_b2, 1);

    lstm_persist<<<128, 288, SMEM_PERSIST>>>(b_ih, b_hh);

    mulv_kernel<<<Bsz, 512>>>(mu_w, mu_b, lv_w, lv_b, eps, out);
    dec_kernel<<<Bsz, 128>>>(dec_w1, dec_b1, dec_w2, dec_b2, out);
}